// round 2
// baseline (speedup 1.0000x reference)
#include <cuda_runtime.h>
#include <cuda_bf16.h>
#include <math.h>

// Problem constants
#define BATCH 32
#define CIN   128
#define HH    64
#define WW    64
#define HW    (HH*WW)          // 4096
#define EMB   384
#define EB    128              // per-branch out channels
#define HID   24               // 384/16

typedef unsigned long long ull;

// packed fp32 FMA: d = a*b + d  (2 lanes)
__device__ __forceinline__ void ffma2(ull& d, ull a, ull b) {
    asm("fma.rn.f32x2 %0, %1, %2, %0;" : "+l"(d) : "l"(a), "l"(b));
}
__device__ __forceinline__ float2 unpack2(ull v) {
    float2 r;
    asm("mov.b64 {%0, %1}, %2;" : "=f"(r.x), "=f"(r.y) : "l"(v));
    return r;
}

// ---------------- scratch (device globals; no allocations allowed) ----------
__device__ float g_fused[(size_t)BATCH * EMB * HW];   // conv concat output [B,E,H,W]
__device__ float g_gout [(size_t)BATCH * EMB * HW];   // 1x1 fusion output  [B,E,H,W]
__device__ float g_avg  [BATCH * EMB];
__device__ float g_max  [BATCH * EMB];
__device__ float g_attn [BATCH * EMB];

// ---------------------------------------------------------------------------
// Kernel 1: direct conv, K in {3,5,7}.  Block = (h, b). 256 threads.
// Each block computes all 128 output channels for one output row (64 w).
// Thread tile: 4 oc x 8 w, with oc paired into f32x2 lanes.
//   - weights staged in shared transposed+paired: s_w2[kk][oc/2] = (w[oc],w[oc+1])
//   - inputs staged duplicated: s_in2[kh][col] = (v,v)
// Inner loop is pure LDS.64 + FFMA2.
// ---------------------------------------------------------------------------
template<int K>
__global__ __launch_bounds__(256, 2)
void conv_kernel(const float* __restrict__ x, const float* __restrict__ wgt,
                 const float* __restrict__ bias, float* __restrict__ out,
                 int ch_off)
{
    constexpr int HALO = K / 2;
    constexpr int WIN  = WW + K - 1;
    constexpr int KK   = K * K;

    __shared__ float2 s_w2[KK][EB / 2];   // paired weights, current c
    __shared__ float2 s_in2[K][WIN];      // duplicated input rows, current c

    const int h = blockIdx.x;
    const int b = blockIdx.y;
    const int t = threadIdx.x;

    const int wg  = t & 7;        // 8 groups of 8 w
    const int ocg = t >> 3;       // 32 groups of 4 oc (= 2 oc-pairs)
    const int w0  = wg * 8;

    ull acc2[2][8];
#pragma unroll
    for (int p = 0; p < 2; ++p)
#pragma unroll
        for (int j = 0; j < 8; ++j) acc2[p][j] = 0ull;

    const float* xb = x + (size_t)b * CIN * HW;

    for (int c = 0; c < CIN; ++c) {
        __syncthreads();
        // stage weights for this input channel: w[oc][c][kh][kw] -> s_w2[kk][oc/2]
        const float* wc = wgt + (size_t)c * KK;
        for (int i = t; i < EB * KK; i += 256) {
            int oc = i / KK;
            int j  = i - oc * KK;
            reinterpret_cast<float*>(&s_w2[j][oc >> 1])[oc & 1] =
                wc[(size_t)oc * CIN * KK + j];
        }
        // stage input rows (zero-padded, duplicated into both f32x2 lanes)
        const float* xc = xb + (size_t)c * HW;
        for (int i = t; i < K * WIN; i += 256) {
            int kh  = i / WIN;
            int col = i - kh * WIN;
            int r   = h - HALO + kh;
            int cc  = col - HALO;
            float v = 0.f;
            if (r >= 0 && r < HH && cc >= 0 && cc < WW) v = xc[r * WW + cc];
            s_in2[kh][col] = make_float2(v, v);
        }
        __syncthreads();

#pragma unroll
        for (int kh = 0; kh < K; ++kh) {
            ull in2[8 + K - 1];
#pragma unroll
            for (int j = 0; j < 8 + K - 1; ++j)
                in2[j] = *reinterpret_cast<const ull*>(&s_in2[kh][w0 + j]);
#pragma unroll
            for (int p = 0; p < 2; ++p) {
#pragma unroll
                for (int kw = 0; kw < K; ++kw) {
                    ull wv = *reinterpret_cast<const ull*>(
                        &s_w2[kh * K + kw][ocg * 2 + p]);
#pragma unroll
                    for (int j = 0; j < 8; ++j)
                        ffma2(acc2[p][j], wv, in2[kw + j]);
                }
            }
        }
    }

    // write: out[b][ch_off+oc][h][w0..w0+8)  (oc = ocg*4 + 2p + {0,1})
#pragma unroll
    for (int p = 0; p < 2; ++p) {
        int oc0 = ocg * 4 + 2 * p;
        float bv0 = bias[oc0];
        float bv1 = bias[oc0 + 1];
        float r0[8], r1[8];
#pragma unroll
        for (int j = 0; j < 8; ++j) {
            float2 u = unpack2(acc2[p][j]);
            r0[j] = u.x + bv0;
            r1[j] = u.y + bv1;
        }
        float* d0 = out + (((size_t)b * EMB + ch_off + oc0) * HH + h) * WW + w0;
        float* d1 = d0 + (size_t)HW;
        *reinterpret_cast<float4*>(d0)     = make_float4(r0[0], r0[1], r0[2], r0[3]);
        *reinterpret_cast<float4*>(d0 + 4) = make_float4(r0[4], r0[5], r0[6], r0[7]);
        *reinterpret_cast<float4*>(d1)     = make_float4(r1[0], r1[1], r1[2], r1[3]);
        *reinterpret_cast<float4*>(d1 + 4) = make_float4(r1[4], r1[5], r1[6], r1[7]);
    }
}

// ---------------------------------------------------------------------------
// Kernel 2: global avg + max pool per (b, e). Block = (e, b), 256 threads.
// ---------------------------------------------------------------------------
__global__ __launch_bounds__(256)
void pool_kernel(const float* __restrict__ fused,
                 float* __restrict__ avg_out, float* __restrict__ max_out)
{
    const int e = blockIdx.x;
    const int b = blockIdx.y;
    const int t = threadIdx.x;

    const float4* p = reinterpret_cast<const float4*>(fused + ((size_t)b * EMB + e) * HW);

    float s = 0.f, m = -INFINITY;
#pragma unroll
    for (int i = 0; i < 4; ++i) {
        float4 v = p[t + i * 256];
        s += v.x + v.y + v.z + v.w;
        m = fmaxf(m, fmaxf(fmaxf(v.x, v.y), fmaxf(v.z, v.w)));
    }

    __shared__ float ss[256], sm[256];
    ss[t] = s; sm[t] = m;
    __syncthreads();
    for (int o = 128; o > 0; o >>= 1) {
        if (t < o) { ss[t] += ss[t + o]; sm[t] = fmaxf(sm[t], sm[t + o]); }
        __syncthreads();
    }
    if (t == 0) {
        avg_out[b * EMB + e] = ss[0] * (1.f / (float)HW);
        max_out[b * EMB + e] = sm[0];
    }
}

// ---------------------------------------------------------------------------
// Kernel 3: CBAM MLP + sigmoid. One block per batch, 384 threads.
// ---------------------------------------------------------------------------
__global__ __launch_bounds__(EMB)
void attn_kernel(const float* __restrict__ avg_in, const float* __restrict__ max_in,
                 const float* __restrict__ w1,      // [HID, EMB]
                 const float* __restrict__ w2,      // [EMB, HID]
                 float* __restrict__ attn)
{
    const int b = blockIdx.x;
    const int t = threadIdx.x;

    __shared__ float s_avg[EMB], s_max[EMB];
    __shared__ float s_h[HID];
    __shared__ float s_ha[HID], s_hm[HID];

    s_avg[t] = avg_in[b * EMB + t];
    s_max[t] = max_in[b * EMB + t];
    __syncthreads();

    if (t < HID) {
        float a = 0.f;
        const float* w1r = w1 + t * EMB;
        for (int e = 0; e < EMB; ++e) a = fmaf(s_avg[e], w1r[e], a);
        s_ha[t] = fmaxf(a, 0.f);
    } else if (t >= 32 && t < 32 + HID) {
        int j = t - 32;
        float a = 0.f;
        const float* w1r = w1 + j * EMB;
        for (int e = 0; e < EMB; ++e) a = fmaf(s_max[e], w1r[e], a);
        s_hm[j] = fmaxf(a, 0.f);
    }
    __syncthreads();
    if (t < HID) s_h[t] = s_ha[t] + s_hm[t];
    __syncthreads();

    float v = 0.f;
    const float* w2r = w2 + t * HID;
#pragma unroll
    for (int j = 0; j < HID; ++j) v = fmaf(s_h[j], w2r[j], v);
    attn[b * EMB + t] = 1.f / (1.f + expf(-v));
}

// ---------------------------------------------------------------------------
// Kernel 4: 1x1 fusion conv as GEMM (f32x2), attn scaling fused into A load.
// g_gout[b,o,hw] = sum_c fused[b,c,hw]*attn[b,c]*Wf[o,c] + fb[o]
// Block tile: 384 o x 32 hw.  Thread tile: 6 o (3 pairs) x 8 hw.
// ---------------------------------------------------------------------------
#define CCHUNK 16
__global__ __launch_bounds__(256, 2)
void fusion_kernel(const float* __restrict__ fused, const float* __restrict__ attn,
                   const float* __restrict__ wf,   // [EMB, EMB] row-major [o][c]
                   const float* __restrict__ fb,
                   float* __restrict__ out)
{
    __shared__ float2 s_wf2[CCHUNK][EMB / 2];   // paired weights [c][o/2]
    __shared__ float2 s_in2[CCHUNK][32];        // duplicated, attn-scaled input

    const int hw0 = blockIdx.x * 32;
    const int b   = blockIdx.y;
    const int t   = threadIdx.x;

    const int hwg = t & 3;        // 4 groups of 8 hw
    const int ocg = t >> 2;       // 64 groups of 6 oc (= 3 pairs)
    const int hwb = hwg * 8;

    ull acc2[3][8];
#pragma unroll
    for (int p = 0; p < 3; ++p)
#pragma unroll
        for (int j = 0; j < 8; ++j) acc2[p][j] = 0ull;

    const float* fb_base = fused + (size_t)b * EMB * HW + hw0;
    const float* attn_b  = attn + b * EMB;

    for (int cb = 0; cb < EMB; cb += CCHUNK) {
        __syncthreads();
        // weights tile: wf[o][cb+c] -> s_wf2[c][o/2]
        for (int i = t; i < EMB * CCHUNK; i += 256) {
            int o = i >> 4;           // /16
            int c = i & 15;
            reinterpret_cast<float*>(&s_wf2[c][o >> 1])[o & 1] =
                wf[(size_t)o * EMB + cb + c];
        }
        // input tile, scaled by attn, duplicated
        for (int i = t; i < CCHUNK * 32; i += 256) {
            int c  = i >> 5;
            int hw = i & 31;
            float v = fb_base[(size_t)(cb + c) * HW + hw] * attn_b[cb + c];
            s_in2[c][hw] = make_float2(v, v);
        }
        __syncthreads();

#pragma unroll
        for (int c = 0; c < CCHUNK; ++c) {
            ull inr[8];
#pragma unroll
            for (int j = 0; j < 8; ++j)
                inr[j] = *reinterpret_cast<const ull*>(&s_in2[c][hwb + j]);
#pragma unroll
            for (int p = 0; p < 3; ++p) {
                ull wv = *reinterpret_cast<const ull*>(&s_wf2[c][ocg * 3 + p]);
#pragma unroll
                for (int j = 0; j < 8; ++j)
                    ffma2(acc2[p][j], wv, inr[j]);
            }
        }
    }

#pragma unroll
    for (int p = 0; p < 3; ++p) {
        int o0 = ocg * 6 + 2 * p;
        float bv0 = fb[o0];
        float bv1 = fb[o0 + 1];
        float r0[8], r1[8];
#pragma unroll
        for (int j = 0; j < 8; ++j) {
            float2 u = unpack2(acc2[p][j]);
            r0[j] = u.x + bv0;
            r1[j] = u.y + bv1;
        }
        float* d0 = out + ((size_t)b * EMB + o0) * HW + hw0 + hwb;
        float* d1 = d0 + (size_t)HW;
        *reinterpret_cast<float4*>(d0)     = make_float4(r0[0], r0[1], r0[2], r0[3]);
        *reinterpret_cast<float4*>(d0 + 4) = make_float4(r0[4], r0[5], r0[6], r0[7]);
        *reinterpret_cast<float4*>(d1)     = make_float4(r1[0], r1[1], r1[2], r1[3]);
        *reinterpret_cast<float4*>(d1 + 4) = make_float4(r1[4], r1[5], r1[6], r1[7]);
    }
}

// ---------------------------------------------------------------------------
// Kernel 5: transpose [B,E,HW] -> [B,HW,E] + LayerNorm over E per token.
// ---------------------------------------------------------------------------
__global__ __launch_bounds__(256)
void ln_kernel(const float* __restrict__ g, const float* __restrict__ gamma,
               const float* __restrict__ beta, float* __restrict__ out)
{
    __shared__ float s[EMB * 17];   // [e][tok] padded (16 tokens + 1)

    const int hw0 = blockIdx.x * 16;
    const int b   = blockIdx.y;
    const int t   = threadIdx.x;

    const float* gb = g + (size_t)b * EMB * HW + hw0;
    for (int i = t; i < EMB * 16; i += 256) {
        int e   = i >> 4;
        int tok = i & 15;
        s[e * 17 + tok] = gb[(size_t)e * HW + tok];
    }
    __syncthreads();

    const int warp = t >> 5;
    const int lane = t & 31;

#pragma unroll
    for (int tt = 0; tt < 2; ++tt) {
        int tok = warp * 2 + tt;
        float vals[12];
        float sum = 0.f, sq = 0.f;
#pragma unroll
        for (int k = 0; k < 12; ++k) {
            float v = s[(lane + 32 * k) * 17 + tok];
            vals[k] = v;
            sum += v;
            sq  = fmaf(v, v, sq);
        }
#pragma unroll
        for (int o = 16; o > 0; o >>= 1) {
            sum += __shfl_xor_sync(0xFFFFFFFFu, sum, o);
            sq  += __shfl_xor_sync(0xFFFFFFFFu, sq,  o);
        }
        float mu  = sum * (1.f / (float)EMB);
        float var = sq * (1.f / (float)EMB) - mu * mu;
        float rstd = rsqrtf(var + 1e-5f);

        float* dst = out + ((size_t)b * HW + hw0 + tok) * EMB;
#pragma unroll
        for (int k = 0; k < 12; ++k) {
            int e = lane + 32 * k;
            dst[e] = (vals[k] - mu) * rstd * gamma[e] + beta[e];
        }
    }
}

// ---------------------------------------------------------------------------
// Launcher.
// ---------------------------------------------------------------------------
extern "C" void kernel_launch(void* const* d_in, const int* in_sizes, int n_in,
                              void* d_out, int out_size)
{
    const float* x   = (const float*)d_in[0];
    const float* w3  = (const float*)d_in[1];
    const float* b3  = (const float*)d_in[2];
    const float* w5  = (const float*)d_in[3];
    const float* b5  = (const float*)d_in[4];
    const float* w7  = (const float*)d_in[5];
    const float* b7  = (const float*)d_in[6];
    const float* cw1 = (const float*)d_in[7];
    const float* cw2 = (const float*)d_in[8];
    const float* fw  = (const float*)d_in[9];
    const float* fbi = (const float*)d_in[10];
    const float* lng = (const float*)d_in[11];
    const float* lnb = (const float*)d_in[12];
    float* out = (float*)d_out;

    float* fused; cudaGetSymbolAddress((void**)&fused, g_fused);
    float* gout;  cudaGetSymbolAddress((void**)&gout,  g_gout);
    float* gavg;  cudaGetSymbolAddress((void**)&gavg,  g_avg);
    float* gmax;  cudaGetSymbolAddress((void**)&gmax,  g_max);
    float* gattn; cudaGetSymbolAddress((void**)&gattn, g_attn);

    dim3 cgrid(HH, BATCH);
    conv_kernel<3><<<cgrid, 256>>>(x, w3, b3, fused, 0);
    conv_kernel<5><<<cgrid, 256>>>(x, w5, b5, fused, EB);
    conv_kernel<7><<<cgrid, 256>>>(x, w7, b7, fused, 2 * EB);

    pool_kernel<<<dim3(EMB, BATCH), 256>>>(fused, gavg, gmax);
    attn_kernel<<<BATCH, EMB>>>(gavg, gmax, cw1, cw2, gattn);

    fusion_kernel<<<dim3(HW / 32, BATCH), 256>>>(fused, gattn, fw, fbi, gout);

    ln_kernel<<<dim3(HW / 16, BATCH), 256>>>(gout, lng, lnb, out);
}

// round 3
// speedup vs baseline: 3.6179x; 3.6179x over previous
#include <cuda_runtime.h>
#include <cuda_bf16.h>
#include <math.h>

// Problem constants
#define BATCH 32
#define CIN   128
#define HH    64
#define WW    64
#define HW    (HH*WW)          // 4096
#define EMB   384
#define EB    128              // per-branch out channels
#define HID   24               // 384/16

// ---------------- scratch (device globals; no allocations allowed) ----------
__device__ float g_fused[(size_t)BATCH * EMB * HW];   // conv concat output [B,E,H,W]
__device__ float g_gout [(size_t)BATCH * EMB * HW];   // 1x1 fusion output  [B,E,H,W]
__device__ float g_avg  [BATCH * EMB];
__device__ float g_max  [BATCH * EMB];
__device__ float g_attn [BATCH * EMB];

// ---- tf32 helpers ----------------------------------------------------------
__device__ __forceinline__ unsigned f2tf32(float v) {
    unsigned u;
    asm("cvt.rna.tf32.f32 %0, %1;" : "=r"(u) : "f"(v));
    return u;
}
__device__ __forceinline__ void mma_tf32(float& d0, float& d1, float& d2, float& d3,
                                         unsigned a0, unsigned a1, unsigned a2, unsigned a3,
                                         unsigned b0, unsigned b1) {
    asm("mma.sync.aligned.m16n8k8.row.col.f32.tf32.tf32.f32 "
        "{%0,%1,%2,%3}, {%4,%5,%6,%7}, {%8,%9}, {%0,%1,%2,%3};"
        : "+f"(d0), "+f"(d1), "+f"(d2), "+f"(d3)
        : "r"(a0), "r"(a1), "r"(a2), "r"(a3), "r"(b0), "r"(b1));
}

// ---------------------------------------------------------------------------
// Kernel 1: implicit-GEMM conv via tf32 mma.sync.  K in {3,5,7}.
// Block = (2 output rows h0..h0+1, batch b): computes 128 oc x (2 x 64) spatial.
// 8 warps; warp w owns oc rows [16w, 16w+16).  n = r*64 + w (0..127): 16 n-tiles.
// Per c-block of 16 channels:
//   - stage zero-padded input rows (tf32) in shared  [c][r][col]
//   - loop over K*K taps; per tap stage W[oc128][c16] (tf32) with a register
//     pipeline (LDG next tap during current tap's mmas)
// Shared layouts chosen so ALL fragment LDS are bank-conflict-free:
//   s_in: c-stride CSTR == 24 (mod 32), row stride 72
//   s_w : [oc][c] stride 20
// ---------------------------------------------------------------------------
template<int K>
__global__ __launch_bounds__(256, 2)
void conv_mma_kernel(const float* __restrict__ x, const float* __restrict__ wgt,
                     const float* __restrict__ bias, float* __restrict__ out,
                     int ch_off)
{
    constexpr int HALO    = K / 2;
    constexpr int WIN     = WW + K - 1;
    constexpr int KK      = K * K;
    constexpr int ROWS    = 2;
    constexpr int IN_ROWS = ROWS + K - 1;
    constexpr int COLPAD  = 72;
    constexpr int CSTRB   = IN_ROWS * COLPAD;
    constexpr int CSTR    = CSTRB + ((24 - (CSTRB & 31)) & 31);   // == 24 mod 32

    __shared__ unsigned s_in[16 * CSTR];
    __shared__ unsigned s_w [128 * 20];

    const int h0  = blockIdx.x * ROWS;
    const int b   = blockIdx.y;
    const int t   = threadIdx.x;
    const int warp = t >> 5;
    const int lane = t & 31;
    const int gid  = lane >> 2;   // group id (0..7)
    const int tig  = lane & 3;    // thread in group
    const int ocb  = warp * 16;

    float d[16][4];
#pragma unroll
    for (int i = 0; i < 16; ++i)
#pragma unroll
        for (int j = 0; j < 4; ++j) d[i][j] = 0.f;

    // per-thread weight staging indices (i = t + j*256 -> oc = i>>4, cc = i&15)
    int w_oc[8], w_cc[8];
#pragma unroll
    for (int j = 0; j < 8; ++j) {
        int i = t + j * 256;
        w_oc[j] = i >> 4;
        w_cc[j] = i & 15;
    }

    for (int c0 = 0; c0 < CIN; c0 += 16) {
        __syncthreads();   // previous compute done: safe to overwrite s_in

        // ---- stage inputs (16 c x IN_ROWS x WIN), tf32, zero-padded ----
        const float* xc = x + ((size_t)b * CIN + c0) * HW;
        for (int i = t; i < 16 * IN_ROWS * WIN; i += 256) {
            int c   = i / (IN_ROWS * WIN);
            int rem = i - c * (IN_ROWS * WIN);
            int r   = rem / WIN;
            int col = rem - r * WIN;
            int gr  = h0 + r - HALO;
            int gw  = col - HALO;
            float v = 0.f;
            if (gr >= 0 && gr < HH && gw >= 0 && gw < WW)
                v = xc[(size_t)c * HW + gr * WW + gw];
            s_in[c * CSTR + r * COLPAD + col] = f2tf32(v);
        }

        // ---- prologue: load weights for tap kk=0 ----
        float wv[8];
#pragma unroll
        for (int j = 0; j < 8; ++j)
            wv[j] = wgt[((size_t)w_oc[j] * CIN + c0 + w_cc[j]) * KK];

        for (int kk = 0; kk < KK; ++kk) {
            __syncthreads();   // prev tap compute done (also: s_in visible on kk=0)
#pragma unroll
            for (int j = 0; j < 8; ++j)
                s_w[w_oc[j] * 20 + w_cc[j]] = f2tf32(wv[j]);

            float wv2[8];
            if (kk + 1 < KK) {
#pragma unroll
                for (int j = 0; j < 8; ++j)
                    wv2[j] = wgt[((size_t)w_oc[j] * CIN + c0 + w_cc[j]) * KK + kk + 1];
            }
            __syncthreads();   // s_w visible

            const int kh = kk / K;
            const int kw = kk - kh * K;

#pragma unroll
            for (int ks = 0; ks < 2; ++ks) {
                const int kb = ks * 8;
                unsigned a0 = s_w[(ocb + gid)     * 20 + kb + tig];
                unsigned a1 = s_w[(ocb + gid + 8) * 20 + kb + tig];
                unsigned a2 = s_w[(ocb + gid)     * 20 + kb + tig + 4];
                unsigned a3 = s_w[(ocb + gid + 8) * 20 + kb + tig + 4];
                const int base_b = (kb + tig) * CSTR + kh * COLPAD + gid + kw;
#pragma unroll
                for (int t16 = 0; t16 < 16; ++t16) {
                    const int r  = t16 >> 3;
                    const int w0 = (t16 & 7) * 8;
                    const int off = base_b + r * COLPAD + w0;
                    unsigned b0 = s_in[off];
                    unsigned b1 = s_in[off + 4 * CSTR];
                    mma_tf32(d[t16][0], d[t16][1], d[t16][2], d[t16][3],
                             a0, a1, a2, a3, b0, b1);
                }
            }
#pragma unroll
            for (int j = 0; j < 8; ++j) wv[j] = wv2[j];
        }
    }

    // ---- epilogue: d(t16)[0,1] -> oc0 row, [2,3] -> oc0+8 row ----
    const int oc0 = ocb + gid;
    const float bv0 = bias[oc0];
    const float bv1 = bias[oc0 + 8];
#pragma unroll
    for (int t16 = 0; t16 < 16; ++t16) {
        const int r  = t16 >> 3;
        const int w0 = (t16 & 7) * 8 + tig * 2;
        const int h  = h0 + r;
        float* p0 = out + (((size_t)b * EMB + ch_off + oc0)     * HH + h) * WW + w0;
        float* p1 = out + (((size_t)b * EMB + ch_off + oc0 + 8) * HH + h) * WW + w0;
        *reinterpret_cast<float2*>(p0) = make_float2(d[t16][0] + bv0, d[t16][1] + bv0);
        *reinterpret_cast<float2*>(p1) = make_float2(d[t16][2] + bv1, d[t16][3] + bv1);
    }
}

// ---------------------------------------------------------------------------
// Kernel 2: global avg + max pool per (b, e). Block = (e, b), 256 threads.
// ---------------------------------------------------------------------------
__global__ __launch_bounds__(256)
void pool_kernel(const float* __restrict__ fused,
                 float* __restrict__ avg_out, float* __restrict__ max_out)
{
    const int e = blockIdx.x;
    const int b = blockIdx.y;
    const int t = threadIdx.x;

    const float4* p = reinterpret_cast<const float4*>(fused + ((size_t)b * EMB + e) * HW);

    float s = 0.f, m = -INFINITY;
#pragma unroll
    for (int i = 0; i < 4; ++i) {
        float4 v = p[t + i * 256];
        s += v.x + v.y + v.z + v.w;
        m = fmaxf(m, fmaxf(fmaxf(v.x, v.y), fmaxf(v.z, v.w)));
    }

    __shared__ float ss[256], sm[256];
    ss[t] = s; sm[t] = m;
    __syncthreads();
    for (int o = 128; o > 0; o >>= 1) {
        if (t < o) { ss[t] += ss[t + o]; sm[t] = fmaxf(sm[t], sm[t + o]); }
        __syncthreads();
    }
    if (t == 0) {
        avg_out[b * EMB + e] = ss[0] * (1.f / (float)HW);
        max_out[b * EMB + e] = sm[0];
    }
}

// ---------------------------------------------------------------------------
// Kernel 3: CBAM MLP + sigmoid. One block per batch, 384 threads.
// ---------------------------------------------------------------------------
__global__ __launch_bounds__(EMB)
void attn_kernel(const float* __restrict__ avg_in, const float* __restrict__ max_in,
                 const float* __restrict__ w1,      // [HID, EMB]
                 const float* __restrict__ w2,      // [EMB, HID]
                 float* __restrict__ attn)
{
    const int b = blockIdx.x;
    const int t = threadIdx.x;

    __shared__ float s_avg[EMB], s_max[EMB];
    __shared__ float s_h[HID];
    __shared__ float s_ha[HID], s_hm[HID];

    s_avg[t] = avg_in[b * EMB + t];
    s_max[t] = max_in[b * EMB + t];
    __syncthreads();

    if (t < HID) {
        float a = 0.f;
        const float* w1r = w1 + t * EMB;
        for (int e = 0; e < EMB; ++e) a = fmaf(s_avg[e], w1r[e], a);
        s_ha[t] = fmaxf(a, 0.f);
    } else if (t >= 32 && t < 32 + HID) {
        int j = t - 32;
        float a = 0.f;
        const float* w1r = w1 + j * EMB;
        for (int e = 0; e < EMB; ++e) a = fmaf(s_max[e], w1r[e], a);
        s_hm[j] = fmaxf(a, 0.f);
    }
    __syncthreads();
    if (t < HID) s_h[t] = s_ha[t] + s_hm[t];
    __syncthreads();

    float v = 0.f;
    const float* w2r = w2 + t * HID;
#pragma unroll
    for (int j = 0; j < HID; ++j) v = fmaf(s_h[j], w2r[j], v);
    attn[b * EMB + t] = 1.f / (1.f + expf(-v));
}

// ---------------------------------------------------------------------------
// Kernel 4: 1x1 fusion conv as tf32 mma GEMM, attn scaling fused into B load.
// out[b][o][hw] = sum_c fused[b][c][hw]*attn[b][c]*Wf[o][c] + fb[o]
// Block: 128 o x 128 hw for one b.  8 warps, warp owns o16.  16 n-tiles.
// c-blocks of 16, register-pipelined staging of both inputs and weights.
// ---------------------------------------------------------------------------
#define XSTR 152    // 128 + 24 : c-stride == 24 mod 32 -> conflict-free B loads
__global__ __launch_bounds__(256, 1)
void fusion_mma_kernel(const float* __restrict__ fused, const float* __restrict__ attn,
                       const float* __restrict__ wf,   // [EMB, EMB] row-major [o][c]
                       const float* __restrict__ fb,
                       float* __restrict__ out)
{
    __shared__ unsigned s_x[16 * XSTR];
    __shared__ unsigned s_w[128 * 20];

    const int obase = blockIdx.x * 128;
    const int hw0   = blockIdx.y * 128;
    const int b     = blockIdx.z;
    const int t     = threadIdx.x;
    const int warp  = t >> 5;
    const int lane  = t & 31;
    const int gid   = lane >> 2;
    const int tig   = lane & 3;
    const int ocb   = warp * 16;

    float d[16][4];
#pragma unroll
    for (int i = 0; i < 16; ++i)
#pragma unroll
        for (int j = 0; j < 4; ++j) d[i][j] = 0.f;

    // staging indices
    int x_cc[2], x_hw[2];          // float4 granules: i4 = t + j*256 -> cc = i4>>5, hw4 = i4&31
#pragma unroll
    for (int j = 0; j < 2; ++j) {
        int i4 = t + j * 256;
        x_cc[j] = i4 >> 5;
        x_hw[j] = (i4 & 31) * 4;
    }
    int w_oc[8], w_cc[8];
#pragma unroll
    for (int j = 0; j < 8; ++j) {
        int i = t + j * 256;
        w_oc[j] = i >> 4;
        w_cc[j] = i & 15;
    }

    const float* xb = fused + (size_t)b * EMB * HW + hw0;
    const float* ab = attn + b * EMB;

    // prologue: load c-block 0
    float4 xv[2];  float wv[8];  float av[2];
#pragma unroll
    for (int j = 0; j < 2; ++j) {
        xv[j] = *reinterpret_cast<const float4*>(xb + (size_t)x_cc[j] * HW + x_hw[j]);
        av[j] = ab[x_cc[j]];
    }
#pragma unroll
    for (int j = 0; j < 8; ++j)
        wv[j] = wf[(size_t)(obase + w_oc[j]) * EMB + w_cc[j]];

    for (int cb = 0; cb < EMB; cb += 16) {
        __syncthreads();   // previous compute done
        // store staged regs (scale + tf32 convert)
#pragma unroll
        for (int j = 0; j < 2; ++j) {
            unsigned* p = &s_x[x_cc[j] * XSTR + x_hw[j]];
            p[0] = f2tf32(xv[j].x * av[j]);
            p[1] = f2tf32(xv[j].y * av[j]);
            p[2] = f2tf32(xv[j].z * av[j]);
            p[3] = f2tf32(xv[j].w * av[j]);
        }
#pragma unroll
        for (int j = 0; j < 8; ++j)
            s_w[w_oc[j] * 20 + w_cc[j]] = f2tf32(wv[j]);

        // prefetch next c-block
        float4 xv2[2]; float wv2[8]; float av2[2];
        const int cn = cb + 16;
        if (cn < EMB) {
#pragma unroll
            for (int j = 0; j < 2; ++j) {
                xv2[j] = *reinterpret_cast<const float4*>(
                    xb + (size_t)(cn + x_cc[j]) * HW + x_hw[j]);
                av2[j] = ab[cn + x_cc[j]];
            }
#pragma unroll
            for (int j = 0; j < 8; ++j)
                wv2[j] = wf[(size_t)(obase + w_oc[j]) * EMB + cn + w_cc[j]];
        }
        __syncthreads();   // tiles visible

#pragma unroll
        for (int ks = 0; ks < 2; ++ks) {
            const int kb = ks * 8;
            unsigned a0 = s_w[(ocb + gid)     * 20 + kb + tig];
            unsigned a1 = s_w[(ocb + gid + 8) * 20 + kb + tig];
            unsigned a2 = s_w[(ocb + gid)     * 20 + kb + tig + 4];
            unsigned a3 = s_w[(ocb + gid + 8) * 20 + kb + tig + 4];
            const int base_b = (kb + tig) * XSTR + gid;
#pragma unroll
            for (int t16 = 0; t16 < 16; ++t16) {
                const int off = base_b + t16 * 8;
                unsigned b0 = s_x[off];
                unsigned b1 = s_x[off + 4 * XSTR];
                mma_tf32(d[t16][0], d[t16][1], d[t16][2], d[t16][3],
                         a0, a1, a2, a3, b0, b1);
            }
        }
#pragma unroll
        for (int j = 0; j < 2; ++j) { xv[j] = xv2[j]; av[j] = av2[j]; }
#pragma unroll
        for (int j = 0; j < 8; ++j) wv[j] = wv2[j];
    }

    // epilogue
    const int o0 = obase + ocb + gid;
    const float bv0 = fb[o0];
    const float bv1 = fb[o0 + 8];
#pragma unroll
    for (int t16 = 0; t16 < 16; ++t16) {
        const int n0 = t16 * 8 + tig * 2;
        float* p0 = out + ((size_t)b * EMB + o0)     * HW + hw0 + n0;
        float* p1 = out + ((size_t)b * EMB + o0 + 8) * HW + hw0 + n0;
        *reinterpret_cast<float2*>(p0) = make_float2(d[t16][0] + bv0, d[t16][1] + bv0);
        *reinterpret_cast<float2*>(p1) = make_float2(d[t16][2] + bv1, d[t16][3] + bv1);
    }
}

// ---------------------------------------------------------------------------
// Kernel 5: transpose [B,E,HW] -> [B,HW,E] + LayerNorm over E per token.
// ---------------------------------------------------------------------------
__global__ __launch_bounds__(256)
void ln_kernel(const float* __restrict__ g, const float* __restrict__ gamma,
               const float* __restrict__ beta, float* __restrict__ out)
{
    __shared__ float s[EMB * 17];

    const int hw0 = blockIdx.x * 16;
    const int b   = blockIdx.y;
    const int t   = threadIdx.x;

    const float* gb = g + (size_t)b * EMB * HW + hw0;
    for (int i = t; i < EMB * 16; i += 256) {
        int e   = i >> 4;
        int tok = i & 15;
        s[e * 17 + tok] = gb[(size_t)e * HW + tok];
    }
    __syncthreads();

    const int warp = t >> 5;
    const int lane = t & 31;

#pragma unroll
    for (int tt = 0; tt < 2; ++tt) {
        int tok = warp * 2 + tt;
        float vals[12];
        float sum = 0.f, sq = 0.f;
#pragma unroll
        for (int k = 0; k < 12; ++k) {
            float v = s[(lane + 32 * k) * 17 + tok];
            vals[k] = v;
            sum += v;
            sq  = fmaf(v, v, sq);
        }
#pragma unroll
        for (int o = 16; o > 0; o >>= 1) {
            sum += __shfl_xor_sync(0xFFFFFFFFu, sum, o);
            sq  += __shfl_xor_sync(0xFFFFFFFFu, sq,  o);
        }
        float mu  = sum * (1.f / (float)EMB);
        float var = sq * (1.f / (float)EMB) - mu * mu;
        float rstd = rsqrtf(var + 1e-5f);

        float* dst = out + ((size_t)b * HW + hw0 + tok) * EMB;
#pragma unroll
        for (int k = 0; k < 12; ++k) {
            int e = lane + 32 * k;
            dst[e] = (vals[k] - mu) * rstd * gamma[e] + beta[e];
        }
    }
}

// ---------------------------------------------------------------------------
// Launcher.
// ---------------------------------------------------------------------------
extern "C" void kernel_launch(void* const* d_in, const int* in_sizes, int n_in,
                              void* d_out, int out_size)
{
    const float* x   = (const float*)d_in[0];
    const float* w3  = (const float*)d_in[1];
    const float* b3  = (const float*)d_in[2];
    const float* w5  = (const float*)d_in[3];
    const float* b5  = (const float*)d_in[4];
    const float* w7  = (const float*)d_in[5];
    const float* b7  = (const float*)d_in[6];
    const float* cw1 = (const float*)d_in[7];
    const float* cw2 = (const float*)d_in[8];
    const float* fw  = (const float*)d_in[9];
    const float* fbi = (const float*)d_in[10];
    const float* lng = (const float*)d_in[11];
    const float* lnb = (const float*)d_in[12];
    float* out = (float*)d_out;

    float* fused; cudaGetSymbolAddress((void**)&fused, g_fused);
    float* gout;  cudaGetSymbolAddress((void**)&gout,  g_gout);
    float* gavg;  cudaGetSymbolAddress((void**)&gavg,  g_avg);
    float* gmax;  cudaGetSymbolAddress((void**)&gmax,  g_max);
    float* gattn; cudaGetSymbolAddress((void**)&gattn, g_attn);

    dim3 cgrid(HH / 2, BATCH);
    conv_mma_kernel<3><<<cgrid, 256>>>(x, w3, b3, fused, 0);
    conv_mma_kernel<5><<<cgrid, 256>>>(x, w5, b5, fused, EB);
    conv_mma_kernel<7><<<cgrid, 256>>>(x, w7, b7, fused, 2 * EB);

    pool_kernel<<<dim3(EMB, BATCH), 256>>>(fused, gavg, gmax);
    attn_kernel<<<BATCH, EMB>>>(gavg, gmax, cw1, cw2, gattn);

    fusion_mma_kernel<<<dim3(EMB / 128, HW / 128, BATCH), 256>>>(fused, gattn, fw, fbi, gout);

    ln_kernel<<<dim3(HW / 16, BATCH), 256>>>(gout, lng, lnb, out);
}

// round 4
// speedup vs baseline: 7.0512x; 1.9490x over previous
#include <cuda_runtime.h>
#include <cuda_bf16.h>
#include <math.h>

// Problem constants
#define BATCH 32
#define CIN   128
#define HH    64
#define WW    64
#define HW    (HH*WW)          // 4096
#define EMB   384
#define EB    128              // per-branch out channels
#define HID   24               // 384/16

// ---------------- scratch (device globals; no allocations allowed) ----------
__device__ float    g_fused[(size_t)BATCH * EMB * HW];   // conv concat output
__device__ float    g_gout [(size_t)BATCH * EMB * HW];   // 1x1 fusion output
__device__ float    g_avg  [BATCH * EMB];
__device__ float    g_max  [BATCH * EMB];
__device__ float    g_attn [BATCH * EMB];
__device__ unsigned g_xt   [(size_t)BATCH * CIN * HW];   // x as tf32 bits
__device__ unsigned g_wt3  [9  * EB * CIN];              // w3 transposed [kk][oc][c], tf32 bits
__device__ unsigned g_wt5  [25 * EB * CIN];
__device__ unsigned g_wt7  [49 * EB * CIN];

// ---- tf32 helpers ----------------------------------------------------------
__device__ __forceinline__ unsigned f2tf32(float v) {
    unsigned u;
    asm("cvt.rna.tf32.f32 %0, %1;" : "=r"(u) : "f"(v));
    return u;
}
__device__ __forceinline__ void mma_tf32(float& d0, float& d1, float& d2, float& d3,
                                         unsigned a0, unsigned a1, unsigned a2, unsigned a3,
                                         unsigned b0, unsigned b1) {
    asm("mma.sync.aligned.m16n8k8.row.col.f32.tf32.tf32.f32 "
        "{%0,%1,%2,%3}, {%4,%5,%6,%7}, {%8,%9}, {%0,%1,%2,%3};"
        : "+f"(d0), "+f"(d1), "+f"(d2), "+f"(d3)
        : "r"(a0), "r"(a1), "r"(a2), "r"(a3), "r"(b0), "r"(b1));
}

// ---------------------------------------------------------------------------
// Pre-pass: convert x to tf32 bits
// ---------------------------------------------------------------------------
__global__ __launch_bounds__(256)
void prep_x_kernel(const float* __restrict__ x, unsigned* __restrict__ xt, int n)
{
    int i = blockIdx.x * 256 + threadIdx.x;
    if (i < n) xt[i] = f2tf32(x[i]);
}

// Pre-pass: transpose weights [oc][c][kk] -> [kk][oc][c], tf32 bits
__global__ __launch_bounds__(256)
void prep_w_kernel(const float* __restrict__ w, unsigned* __restrict__ wt, int kkN)
{
    int idx = blockIdx.x * 256 + threadIdx.x;
    int total = kkN * EB * CIN;
    if (idx < total) {
        int c  = idx & 127;
        int oc = (idx >> 7) & 127;
        int kk = idx >> 14;
        wt[idx] = f2tf32(w[((size_t)oc * CIN + c) * kkN + kk]);
    }
}

// ---------------------------------------------------------------------------
// Conv via tf32 mma, restructured:
//  - c-chunk 8 (= one mma K step)
//  - weights for a whole kh-row (K taps) staged per barrier pair, register-
//    prefetched one group ahead (LDG issued before sync, consumed next group)
//  - warp tile 32 oc x 64 sp (one full output row per warp)
// Template: K, ROWS (output rows per block), OCB (oc per block)
// ---------------------------------------------------------------------------
template<int K, int ROWS, int OCB>
__global__ __launch_bounds__(256, 2)
void conv_mma2_kernel(const unsigned* __restrict__ xt, const unsigned* __restrict__ wt,
                      const float* __restrict__ bias, float* __restrict__ out, int ch_off)
{
    constexpr int HALO    = K / 2;
    constexpr int WIN     = WW + K - 1;
    constexpr int IN_ROWS = ROWS + K - 1;
    constexpr int COLPAD  = WIN;
    constexpr int CSTRB   = IN_ROWS * COLPAD;
    constexpr int R32     = CSTRB & 31;
    constexpr int P8      = (8 - R32) & 31;
    constexpr int P24     = (24 - R32) & 31;
    constexpr int CSTR    = CSTRB + (P8 < P24 ? P8 : P24);   // ≡ 8 or 24 mod 32
    constexpr int NOG     = OCB / 32;     // warp oc-groups
    constexpr int NSG     = 8 / NOG;      // warp spatial-groups (== ROWS)
    constexpr int NITEM   = K * OCB;      // weight items per group (tap, oc)
    constexpr int NPF     = (NITEM + 255) / 256;

    __shared__ unsigned s_in[8 * CSTR];
    __shared__ __align__(16) unsigned s_w[K * OCB * 12];

    const int h0     = blockIdx.x * ROWS;
    const int b      = blockIdx.y;
    const int ocbase = blockIdx.z * OCB;
    const int t      = threadIdx.x;
    const int warp   = t >> 5;
    const int lane   = t & 31;
    const int gid    = lane >> 2;
    const int tig    = lane & 3;
    const int ocg    = warp / NSG;
    const int rw     = warp % NSG;

    float d[2][8][4];
#pragma unroll
    for (int mm = 0; mm < 2; ++mm)
#pragma unroll
        for (int n = 0; n < 8; ++n)
#pragma unroll
            for (int j = 0; j < 4; ++j) d[mm][n][j] = 0.f;

    uint4 wra[NPF], wrb[NPF];

    // prologue: prefetch group 0 (kh=0), c-block 0
#pragma unroll
    for (int j = 0; j < NPF; ++j) {
        int it = t + j * 256;
        if (it < NITEM) {
            int tap = it / OCB, oc = it - tap * OCB;
            const uint4* src = reinterpret_cast<const uint4*>(
                wt + ((size_t)tap * EB + ocbase + oc) * CIN);
            wra[j] = src[0];
            wrb[j] = src[1];
        }
    }

    for (int c0 = 0; c0 < CIN; c0 += 8) {
        // ---- stage inputs: 8 c x IN_ROWS x WIN (zero-padded tf32 bits) ----
        const unsigned* xc = xt + ((size_t)b * CIN + c0) * HW;
        for (int i = t; i < 8 * IN_ROWS * WIN; i += 256) {
            int c   = i / (IN_ROWS * WIN);
            int rem = i - c * (IN_ROWS * WIN);
            int r   = rem / WIN;
            int col = rem - r * WIN;
            int gr  = h0 + r - HALO;
            int gw  = col - HALO;
            unsigned v = 0u;
            if ((unsigned)gr < HH && (unsigned)gw < WW)
                v = xc[(size_t)c * HW + gr * WW + gw];
            s_in[c * CSTR + r * COLPAD + col] = v;
        }

#pragma unroll
        for (int g = 0; g < K; ++g) {
            // store this group's prefetched weights (s_w safe: prior readers
            // finished before trailing sync of previous group)
#pragma unroll
            for (int j = 0; j < NPF; ++j) {
                int it = t + j * 256;
                if (it < NITEM) {
                    int tap = it / OCB, oc = it - tap * OCB;
                    unsigned dst = (unsigned)(tap * OCB + oc) * 12;
                    *reinterpret_cast<uint4*>(&s_w[dst])     = wra[j];
                    *reinterpret_cast<uint4*>(&s_w[dst + 4]) = wrb[j];
                }
            }
            // issue prefetch for next group (lands during this group's mmas)
            {
                int gn = g + 1, cn = c0;
                if (gn == K) { gn = 0; cn = c0 + 8; }
                if (cn < CIN) {
#pragma unroll
                    for (int j = 0; j < NPF; ++j) {
                        int it = t + j * 256;
                        if (it < NITEM) {
                            int tap = it / OCB, oc = it - tap * OCB;
                            const uint4* src = reinterpret_cast<const uint4*>(
                                wt + ((size_t)(gn * K + tap) * EB + ocbase + oc) * CIN + cn);
                            wra[j] = src[0];
                            wrb[j] = src[1];
                        }
                    }
                }
            }
            __syncthreads();   // s_w (and on g==0: s_in) visible

            // ---- mma over the K taps of kh-row g ----
#pragma unroll
            for (int kw = 0; kw < K; ++kw) {
                unsigned a[2][4];
#pragma unroll
                for (int mm = 0; mm < 2; ++mm) {
                    int row = kw * OCB + ocg * 32 + mm * 16 + gid;
                    a[mm][0] = s_w[row * 12 + tig];
                    a[mm][1] = s_w[(row + 8) * 12 + tig];
                    a[mm][2] = s_w[row * 12 + tig + 4];
                    a[mm][3] = s_w[(row + 8) * 12 + tig + 4];
                }
                const int boff = tig * CSTR + (rw + g) * COLPAD + gid + kw;
#pragma unroll
                for (int n = 0; n < 8; ++n) {
                    unsigned b0 = s_in[boff + n * 8];
                    unsigned b1 = s_in[boff + n * 8 + 4 * CSTR];
                    mma_tf32(d[0][n][0], d[0][n][1], d[0][n][2], d[0][n][3],
                             a[0][0], a[0][1], a[0][2], a[0][3], b0, b1);
                    mma_tf32(d[1][n][0], d[1][n][1], d[1][n][2], d[1][n][3],
                             a[1][0], a[1][1], a[1][2], a[1][3], b0, b1);
                }
            }
            __syncthreads();   // group done: s_w (and s_in on last g) reusable
        }
    }

    // ---- epilogue ----
    const int h = h0 + rw;
#pragma unroll
    for (int mm = 0; mm < 2; ++mm) {
        int ocl = ocg * 32 + mm * 16 + gid;
        int oc0 = ocbase + ocl;
        float bv0 = bias[oc0];
        float bv1 = bias[oc0 + 8];
#pragma unroll
        for (int n = 0; n < 8; ++n) {
            int w0 = n * 8 + tig * 2;
            float* p0 = out + (((size_t)b * EMB + ch_off + oc0) * HH + h) * WW + w0;
            float* p1 = p0 + (size_t)8 * HW;
            *reinterpret_cast<float2*>(p0) = make_float2(d[mm][n][0] + bv0, d[mm][n][1] + bv0);
            *reinterpret_cast<float2*>(p1) = make_float2(d[mm][n][2] + bv1, d[mm][n][3] + bv1);
        }
    }
}

// ---------------------------------------------------------------------------
// Global avg + max pool per (b, e).
// ---------------------------------------------------------------------------
__global__ __launch_bounds__(256)
void pool_kernel(const float* __restrict__ fused,
                 float* __restrict__ avg_out, float* __restrict__ max_out)
{
    const int e = blockIdx.x;
    const int b = blockIdx.y;
    const int t = threadIdx.x;

    const float4* p = reinterpret_cast<const float4*>(fused + ((size_t)b * EMB + e) * HW);

    float s = 0.f, m = -INFINITY;
#pragma unroll
    for (int i = 0; i < 4; ++i) {
        float4 v = p[t + i * 256];
        s += v.x + v.y + v.z + v.w;
        m = fmaxf(m, fmaxf(fmaxf(v.x, v.y), fmaxf(v.z, v.w)));
    }

    __shared__ float ss[256], sm[256];
    ss[t] = s; sm[t] = m;
    __syncthreads();
    for (int o = 128; o > 0; o >>= 1) {
        if (t < o) { ss[t] += ss[t + o]; sm[t] = fmaxf(sm[t], sm[t + o]); }
        __syncthreads();
    }
    if (t == 0) {
        avg_out[b * EMB + e] = ss[0] * (1.f / (float)HW);
        max_out[b * EMB + e] = sm[0];
    }
}

// ---------------------------------------------------------------------------
// CBAM MLP + sigmoid.
// ---------------------------------------------------------------------------
__global__ __launch_bounds__(EMB)
void attn_kernel(const float* __restrict__ avg_in, const float* __restrict__ max_in,
                 const float* __restrict__ w1, const float* __restrict__ w2,
                 float* __restrict__ attn)
{
    const int b = blockIdx.x;
    const int t = threadIdx.x;

    __shared__ float s_avg[EMB], s_max[EMB];
    __shared__ float s_h[HID];
    __shared__ float s_ha[HID], s_hm[HID];

    s_avg[t] = avg_in[b * EMB + t];
    s_max[t] = max_in[b * EMB + t];
    __syncthreads();

    if (t < HID) {
        float a = 0.f;
        const float* w1r = w1 + t * EMB;
        for (int e = 0; e < EMB; ++e) a = fmaf(s_avg[e], w1r[e], a);
        s_ha[t] = fmaxf(a, 0.f);
    } else if (t >= 32 && t < 32 + HID) {
        int j = t - 32;
        float a = 0.f;
        const float* w1r = w1 + j * EMB;
        for (int e = 0; e < EMB; ++e) a = fmaf(s_max[e], w1r[e], a);
        s_hm[j] = fmaxf(a, 0.f);
    }
    __syncthreads();
    if (t < HID) s_h[t] = s_ha[t] + s_hm[t];
    __syncthreads();

    float v = 0.f;
    const float* w2r = w2 + t * HID;
#pragma unroll
    for (int j = 0; j < HID; ++j) v = fmaf(s_h[j], w2r[j], v);
    attn[b * EMB + t] = 1.f / (1.f + expf(-v));
}

// ---------------------------------------------------------------------------
// 1x1 fusion conv as tf32 mma GEMM, attn fused into B load (unchanged).
// ---------------------------------------------------------------------------
#define XSTR 152
__global__ __launch_bounds__(256, 1)
void fusion_mma_kernel(const float* __restrict__ fused, const float* __restrict__ attn,
                       const float* __restrict__ wf, const float* __restrict__ fb,
                       float* __restrict__ out)
{
    __shared__ unsigned s_x[16 * XSTR];
    __shared__ unsigned s_w[128 * 20];

    const int obase = blockIdx.x * 128;
    const int hw0   = blockIdx.y * 128;
    const int b     = blockIdx.z;
    const int t     = threadIdx.x;
    const int warp  = t >> 5;
    const int lane  = t & 31;
    const int gid   = lane >> 2;
    const int tig   = lane & 3;
    const int ocb   = warp * 16;

    float d[16][4];
#pragma unroll
    for (int i = 0; i < 16; ++i)
#pragma unroll
        for (int j = 0; j < 4; ++j) d[i][j] = 0.f;

    int x_cc[2], x_hw[2];
#pragma unroll
    for (int j = 0; j < 2; ++j) {
        int i4 = t + j * 256;
        x_cc[j] = i4 >> 5;
        x_hw[j] = (i4 & 31) * 4;
    }
    int w_oc[8], w_cc[8];
#pragma unroll
    for (int j = 0; j < 8; ++j) {
        int i = t + j * 256;
        w_oc[j] = i >> 4;
        w_cc[j] = i & 15;
    }

    const float* xb = fused + (size_t)b * EMB * HW + hw0;
    const float* ab = attn + b * EMB;

    float4 xv[2];  float wv[8];  float av[2];
#pragma unroll
    for (int j = 0; j < 2; ++j) {
        xv[j] = *reinterpret_cast<const float4*>(xb + (size_t)x_cc[j] * HW + x_hw[j]);
        av[j] = ab[x_cc[j]];
    }
#pragma unroll
    for (int j = 0; j < 8; ++j)
        wv[j] = wf[(size_t)(obase + w_oc[j]) * EMB + w_cc[j]];

    for (int cb = 0; cb < EMB; cb += 16) {
        __syncthreads();
#pragma unroll
        for (int j = 0; j < 2; ++j) {
            unsigned* p = &s_x[x_cc[j] * XSTR + x_hw[j]];
            p[0] = f2tf32(xv[j].x * av[j]);
            p[1] = f2tf32(xv[j].y * av[j]);
            p[2] = f2tf32(xv[j].z * av[j]);
            p[3] = f2tf32(xv[j].w * av[j]);
        }
#pragma unroll
        for (int j = 0; j < 8; ++j)
            s_w[w_oc[j] * 20 + w_cc[j]] = f2tf32(wv[j]);

        float4 xv2[2]; float wv2[8]; float av2[2];
        const int cn = cb + 16;
        if (cn < EMB) {
#pragma unroll
            for (int j = 0; j < 2; ++j) {
                xv2[j] = *reinterpret_cast<const float4*>(
                    xb + (size_t)(cn + x_cc[j]) * HW + x_hw[j]);
                av2[j] = ab[cn + x_cc[j]];
            }
#pragma unroll
            for (int j = 0; j < 8; ++j)
                wv2[j] = wf[(size_t)(obase + w_oc[j]) * EMB + cn + w_cc[j]];
        }
        __syncthreads();

#pragma unroll
        for (int ks = 0; ks < 2; ++ks) {
            const int kb = ks * 8;
            unsigned a0 = s_w[(ocb + gid)     * 20 + kb + tig];
            unsigned a1 = s_w[(ocb + gid + 8) * 20 + kb + tig];
            unsigned a2 = s_w[(ocb + gid)     * 20 + kb + tig + 4];
            unsigned a3 = s_w[(ocb + gid + 8) * 20 + kb + tig + 4];
            const int base_b = (kb + tig) * XSTR + gid;
#pragma unroll
            for (int t16 = 0; t16 < 16; ++t16) {
                const int off = base_b + t16 * 8;
                unsigned b0 = s_x[off];
                unsigned b1 = s_x[off + 4 * XSTR];
                mma_tf32(d[t16][0], d[t16][1], d[t16][2], d[t16][3],
                         a0, a1, a2, a3, b0, b1);
            }
        }
#pragma unroll
        for (int j = 0; j < 2; ++j) { xv[j] = xv2[j]; av[j] = av2[j]; }
#pragma unroll
        for (int j = 0; j < 8; ++j) wv[j] = wv2[j];
    }

    const int o0 = obase + ocb + gid;
    const float bv0 = fb[o0];
    const float bv1 = fb[o0 + 8];
#pragma unroll
    for (int t16 = 0; t16 < 16; ++t16) {
        const int n0 = t16 * 8 + tig * 2;
        float* p0 = out + ((size_t)b * EMB + o0)     * HW + hw0 + n0;
        float* p1 = out + ((size_t)b * EMB + o0 + 8) * HW + hw0 + n0;
        *reinterpret_cast<float2*>(p0) = make_float2(d[t16][0] + bv0, d[t16][1] + bv0);
        *reinterpret_cast<float2*>(p1) = make_float2(d[t16][2] + bv1, d[t16][3] + bv1);
    }
}

// ---------------------------------------------------------------------------
// Transpose [B,E,HW] -> [B,HW,E] + LayerNorm over E.
// ---------------------------------------------------------------------------
__global__ __launch_bounds__(256)
void ln_kernel(const float* __restrict__ g, const float* __restrict__ gamma,
               const float* __restrict__ beta, float* __restrict__ out)
{
    __shared__ float s[EMB * 17];

    const int hw0 = blockIdx.x * 16;
    const int b   = blockIdx.y;
    const int t   = threadIdx.x;

    const float* gb = g + (size_t)b * EMB * HW + hw0;
    for (int i = t; i < EMB * 16; i += 256) {
        int e   = i >> 4;
        int tok = i & 15;
        s[e * 17 + tok] = gb[(size_t)e * HW + tok];
    }
    __syncthreads();

    const int warp = t >> 5;
    const int lane = t & 31;

#pragma unroll
    for (int tt = 0; tt < 2; ++tt) {
        int tok = warp * 2 + tt;
        float vals[12];
        float sum = 0.f, sq = 0.f;
#pragma unroll
        for (int k = 0; k < 12; ++k) {
            float v = s[(lane + 32 * k) * 17 + tok];
            vals[k] = v;
            sum += v;
            sq  = fmaf(v, v, sq);
        }
#pragma unroll
        for (int o = 16; o > 0; o >>= 1) {
            sum += __shfl_xor_sync(0xFFFFFFFFu, sum, o);
            sq  += __shfl_xor_sync(0xFFFFFFFFu, sq,  o);
        }
        float mu  = sum * (1.f / (float)EMB);
        float var = sq * (1.f / (float)EMB) - mu * mu;
        float rstd = rsqrtf(var + 1e-5f);

        float* dst = out + ((size_t)b * HW + hw0 + tok) * EMB;
#pragma unroll
        for (int k = 0; k < 12; ++k) {
            int e = lane + 32 * k;
            dst[e] = (vals[k] - mu) * rstd * gamma[e] + beta[e];
        }
    }
}

// ---------------------------------------------------------------------------
// Launcher.
// ---------------------------------------------------------------------------
extern "C" void kernel_launch(void* const* d_in, const int* in_sizes, int n_in,
                              void* d_out, int out_size)
{
    const float* x   = (const float*)d_in[0];
    const float* w3  = (const float*)d_in[1];
    const float* b3  = (const float*)d_in[2];
    const float* w5  = (const float*)d_in[3];
    const float* b5  = (const float*)d_in[4];
    const float* w7  = (const float*)d_in[5];
    const float* b7  = (const float*)d_in[6];
    const float* cw1 = (const float*)d_in[7];
    const float* cw2 = (const float*)d_in[8];
    const float* fw  = (const float*)d_in[9];
    const float* fbi = (const float*)d_in[10];
    const float* lng = (const float*)d_in[11];
    const float* lnb = (const float*)d_in[12];
    float* out = (float*)d_out;

    float* fused; cudaGetSymbolAddress((void**)&fused, g_fused);
    float* gout;  cudaGetSymbolAddress((void**)&gout,  g_gout);
    float* gavg;  cudaGetSymbolAddress((void**)&gavg,  g_avg);
    float* gmax;  cudaGetSymbolAddress((void**)&gmax,  g_max);
    float* gattn; cudaGetSymbolAddress((void**)&gattn, g_attn);
    unsigned* xt;  cudaGetSymbolAddress((void**)&xt,  g_xt);
    unsigned* wt3; cudaGetSymbolAddress((void**)&wt3, g_wt3);
    unsigned* wt5; cudaGetSymbolAddress((void**)&wt5, g_wt5);
    unsigned* wt7; cudaGetSymbolAddress((void**)&wt7, g_wt7);

    // pre-pass conversions
    const int nx = BATCH * CIN * HW;
    prep_x_kernel<<<(nx + 255) / 256, 256>>>(x, xt, nx);
    prep_w_kernel<<<(9  * EB * CIN + 255) / 256, 256>>>(w3, wt3, 9);
    prep_w_kernel<<<(25 * EB * CIN + 255) / 256, 256>>>(w5, wt5, 25);
    prep_w_kernel<<<(49 * EB * CIN + 255) / 256, 256>>>(w7, wt7, 49);

    // convs: K3/K5 -> 128oc x 2rows blocks; K7 -> 64oc x 4rows blocks
    conv_mma2_kernel<3, 2, 128><<<dim3(HH / 2, BATCH, 1), 256>>>(xt, wt3, b3, fused, 0);
    conv_mma2_kernel<5, 2, 128><<<dim3(HH / 2, BATCH, 1), 256>>>(xt, wt5, b5, fused, EB);
    conv_mma2_kernel<7, 4, 64><<<dim3(HH / 4, BATCH, 2), 256>>>(xt, wt7, b7, fused, 2 * EB);

    pool_kernel<<<dim3(EMB, BATCH), 256>>>(fused, gavg, gmax);
    attn_kernel<<<BATCH, EMB>>>(gavg, gmax, cw1, cw2, gattn);

    fusion_mma_kernel<<<dim3(EMB / 128, HW / 128, BATCH), 256>>>(fused, gattn, fw, fbi, gout);

    ln_kernel<<<dim3(HW / 16, BATCH), 256>>>(gout, lng, lnb, out);
}

// round 5
// speedup vs baseline: 12.3267x; 1.7482x over previous
#include <cuda_runtime.h>
#include <cuda_fp16.h>
#include <cuda_bf16.h>
#include <math.h>

// Problem constants
#define BATCH 32
#define CIN   128
#define CB16  (CIN/16)         // 8 c-blocks of 16
#define HH    64
#define WW    64
#define HW    (HH*WW)          // 4096
#define EMB   384
#define EB    128              // per-branch out channels
#define HID   24               // 384/16

// ---------------- scratch (device globals; no allocations allowed) ----------
__device__ float  g_fused[(size_t)BATCH * EMB * HW];   // conv concat output
__device__ float  g_gout [(size_t)BATCH * EMB * HW];   // 1x1 fusion output
__device__ float  g_avg  [BATCH * EMB];
__device__ float  g_max  [BATCH * EMB];
__device__ float  g_attn [BATCH * EMB];
__device__ __half g_xh   [(size_t)BATCH * CB16 * HW * 16];  // x fp16, [b][cb][h][w][c16]
__device__ __half g_wh3  [9  * EB * CIN];              // w fp16, [tap][oc][c]
__device__ __half g_wh5  [25 * EB * CIN];
__device__ __half g_wh7  [49 * EB * CIN];

// ---- helpers ---------------------------------------------------------------
__device__ __forceinline__ unsigned f2tf32(float v) {
    unsigned u;
    asm("cvt.rna.tf32.f32 %0, %1;" : "=r"(u) : "f"(v));
    return u;
}
__device__ __forceinline__ void mma_tf32(float& d0, float& d1, float& d2, float& d3,
                                         unsigned a0, unsigned a1, unsigned a2, unsigned a3,
                                         unsigned b0, unsigned b1) {
    asm("mma.sync.aligned.m16n8k8.row.col.f32.tf32.tf32.f32 "
        "{%0,%1,%2,%3}, {%4,%5,%6,%7}, {%8,%9}, {%0,%1,%2,%3};"
        : "+f"(d0), "+f"(d1), "+f"(d2), "+f"(d3)
        : "r"(a0), "r"(a1), "r"(a2), "r"(a3), "r"(b0), "r"(b1));
}
__device__ __forceinline__ void mma_f16(float& d0, float& d1, float& d2, float& d3,
                                        unsigned a0, unsigned a1, unsigned a2, unsigned a3,
                                        unsigned b0, unsigned b1) {
    asm("mma.sync.aligned.m16n8k16.row.col.f32.f16.f16.f32 "
        "{%0,%1,%2,%3}, {%4,%5,%6,%7}, {%8,%9}, {%0,%1,%2,%3};"
        : "+f"(d0), "+f"(d1), "+f"(d2), "+f"(d3)
        : "r"(a0), "r"(a1), "r"(a2), "r"(a3), "r"(b0), "r"(b1));
}
__device__ __forceinline__ void ldsm_x4(unsigned& r0, unsigned& r1, unsigned& r2, unsigned& r3,
                                        unsigned addr) {
    asm volatile("ldmatrix.sync.aligned.m8n8.x4.shared.b16 {%0,%1,%2,%3}, [%4];"
                 : "=r"(r0), "=r"(r1), "=r"(r2), "=r"(r3) : "r"(addr));
}
__device__ __forceinline__ void ldsm_x2(unsigned& r0, unsigned& r1, unsigned addr) {
    asm volatile("ldmatrix.sync.aligned.m8n8.x2.shared.b16 {%0,%1}, [%2];"
                 : "=r"(r0), "=r"(r1) : "r"(addr));
}

// ---------------------------------------------------------------------------
// Pre-pass: x [B][C][H][W] fp32 -> g_xh [b][cb][h][w][c16] fp16 (tiled transpose)
// ---------------------------------------------------------------------------
__global__ __launch_bounds__(256)
void prep_xh_kernel(const float* __restrict__ x, __half* __restrict__ xh)
{
    __shared__ __half s[16][129];
    const int hw0 = blockIdx.x * 128;
    const int cb  = blockIdx.y;
    const int b   = blockIdx.z;
    const int t   = threadIdx.x;

#pragma unroll
    for (int p = 0; p < 8; ++p) {
        int ci = p * 2 + (t >> 7);
        int j  = t & 127;
        s[ci][j] = __float2half(x[((size_t)(b * CIN + cb * 16 + ci)) * HW + hw0 + j]);
    }
    __syncthreads();

    // one pass: 256 chunks of 8 halves
    int j    = t >> 1;
    int csel = t & 1;
    __half tmp[8];
#pragma unroll
    for (int k = 0; k < 8; ++k) tmp[k] = s[csel * 8 + k][j];
    *reinterpret_cast<uint4*>(&xh[(((size_t)(b * CB16 + cb)) * HW + hw0 + j) * 16 + csel * 8]) =
        *reinterpret_cast<uint4*>(tmp);
}

// Pre-pass: w [oc][c][kk] fp32 -> wh [kk][oc][c] fp16
__global__ __launch_bounds__(256)
void prep_wh_kernel(const float* __restrict__ w, __half* __restrict__ wh, int kkN)
{
    int idx = blockIdx.x * 256 + threadIdx.x;
    int total = kkN * EB * CIN;
    if (idx < total) {
        int c  = idx & 127;
        int oc = (idx >> 7) & 127;
        int kk = idx >> 14;
        wh[idx] = __float2half(w[((size_t)oc * CIN + c) * kkN + kk]);
    }
}

// ---------------------------------------------------------------------------
// Conv via fp16 mma m16n8k16 + ldmatrix.
//  - c-block 16 (= one mma K step); inputs staged as [n = r*WIN+col][c16] fp16
//    with XOR-16B swizzle (conflict-free for any consecutive-8 col window)
//  - weights staged per kh-group: [kw][oc][c16] with same swizzle, register-
//    prefetched one group ahead
//  - warp tile 32 oc x 64 spatial; per tap: 2 LDSM.x4 + 8 LDSM.x2 + 16 mma
// ---------------------------------------------------------------------------
template<int K, int ROWS, int OCB>
__global__ __launch_bounds__(256, 2)
void conv_f16_kernel(const __half* __restrict__ xh, const __half* __restrict__ wh,
                     const float* __restrict__ bias, float* __restrict__ out, int ch_off)
{
    constexpr int HALO    = K / 2;
    constexpr int WIN     = WW + K - 1;
    constexpr int IN_ROWS = ROWS + K - 1;
    constexpr int NSG     = ROWS;          // warp spatial groups
    constexpr int NITEM   = K * OCB;       // weight granules per kh-group
    constexpr int NPF     = (NITEM + 255) / 256;
    constexpr int NCHUNK  = IN_ROWS * WIN * 2;

    __shared__ __align__(16) unsigned char s_in_raw[IN_ROWS * WIN * 32];
    __shared__ __align__(16) unsigned char s_w_raw [K * OCB * 32];

    const int h0     = blockIdx.x * ROWS;
    const int b      = blockIdx.y;
    const int ocbase = blockIdx.z * OCB;
    const int t      = threadIdx.x;
    const int warp   = t >> 5;
    const int lane   = t & 31;
    const int gid    = lane >> 2;
    const int tig    = lane & 3;
    const int ocg    = warp / NSG;
    const int rw     = warp % NSG;

    const unsigned s_in_base = (unsigned)__cvta_generic_to_shared(s_in_raw);
    const unsigned s_w_base  = (unsigned)__cvta_generic_to_shared(s_w_raw);

    float d[2][8][4];
#pragma unroll
    for (int mm = 0; mm < 2; ++mm)
#pragma unroll
        for (int n = 0; n < 8; ++n)
#pragma unroll
            for (int j = 0; j < 4; ++j) d[mm][n][j] = 0.f;

    // lane-constant fragment address components
    const int laneA  = lane & 15;          // A row within 16
    const int cselA  = (lane >> 4) & 1;
    const int laneB  = lane & 7;           // B col within 8
    const int cselB  = (lane >> 3) & 1;

    uint4 wra[NPF], wrb[NPF];

    // prologue: prefetch kh-group 0, c-block 0
#pragma unroll
    for (int j = 0; j < NPF; ++j) {
        int it = t + j * 256;
        if (it < NITEM) {
            int tap = it / OCB, oc = it - tap * OCB;
            const uint4* src = reinterpret_cast<const uint4*>(
                wh + ((size_t)tap * EB + ocbase + oc) * CIN);
            wra[j] = src[0];
            wrb[j] = src[1];
        }
    }

    for (int cb = 0; cb < CB16; ++cb) {
        // ---- stage inputs: [n][c16] fp16, swizzled, zero-padded ----
        const __half* xc = xh + ((size_t)(b * CB16 + cb)) * HW * 16;
        for (int q = t; q < NCHUNK; q += 256) {
            int n    = q >> 1;
            int csel = q & 1;
            int r    = n / WIN;
            int col  = n - r * WIN;
            int gr   = h0 + r - HALO;
            int gw   = col - HALO;
            uint4 v = make_uint4(0u, 0u, 0u, 0u);
            if ((unsigned)gr < HH && (unsigned)gw < WW)
                v = *reinterpret_cast<const uint4*>(xc + ((size_t)gr * WW + gw) * 16 + csel * 8);
            unsigned off = (unsigned)(n * 32 + csel * 16) ^ ((n & 4) << 2);
            *reinterpret_cast<uint4*>(s_in_raw + off) = v;
        }

#pragma unroll
        for (int g = 0; g < K; ++g) {
            // store this group's prefetched weights
#pragma unroll
            for (int j = 0; j < NPF; ++j) {
                int it = t + j * 256;
                if (it < NITEM) {
                    unsigned sw  = (unsigned)((it & 4) << 2);
                    *reinterpret_cast<uint4*>(s_w_raw + ((unsigned)(it * 32)      ^ sw)) = wra[j];
                    *reinterpret_cast<uint4*>(s_w_raw + ((unsigned)(it * 32 + 16) ^ sw)) = wrb[j];
                }
            }
            // prefetch next group
            {
                int gn = g + 1, cn = cb;
                if (gn == K) { gn = 0; cn = cb + 1; }
                if (cn < CB16) {
#pragma unroll
                    for (int j = 0; j < NPF; ++j) {
                        int it = t + j * 256;
                        if (it < NITEM) {
                            int tap = it / OCB, oc = it - tap * OCB;
                            const uint4* src = reinterpret_cast<const uint4*>(
                                wh + ((size_t)(gn * K + tap) * EB + ocbase + oc) * CIN + cn * 16);
                            wra[j] = src[0];
                            wrb[j] = src[1];
                        }
                    }
                }
            }
            __syncthreads();   // s_w (and on g==0: s_in) visible

            const int rowbase = (rw + g) * WIN;
#pragma unroll
            for (int kw = 0; kw < K; ++kw) {
                unsigned a[2][4];
#pragma unroll
                for (int mm = 0; mm < 2; ++mm) {
                    int gA = kw * OCB + ocg * 32 + mm * 16 + laneA;
                    unsigned offA = (unsigned)(gA * 32 + cselA * 16) ^ ((gA & 4) << 2);
                    ldsm_x4(a[mm][0], a[mm][1], a[mm][2], a[mm][3], s_w_base + offA);
                }
#pragma unroll
                for (int nt = 0; nt < 8; ++nt) {
                    int gB = rowbase + nt * 8 + laneB + kw;
                    unsigned offB = (unsigned)(gB * 32 + cselB * 16) ^ ((gB & 4) << 2);
                    unsigned b0, b1;
                    ldsm_x2(b0, b1, s_in_base + offB);
                    mma_f16(d[0][nt][0], d[0][nt][1], d[0][nt][2], d[0][nt][3],
                            a[0][0], a[0][1], a[0][2], a[0][3], b0, b1);
                    mma_f16(d[1][nt][0], d[1][nt][1], d[1][nt][2], d[1][nt][3],
                            a[1][0], a[1][1], a[1][2], a[1][3], b0, b1);
                }
            }
            __syncthreads();   // group done: s_w (and s_in on last g) reusable
        }
    }

    // ---- epilogue ----
    const int h = h0 + rw;
#pragma unroll
    for (int mm = 0; mm < 2; ++mm) {
        int oc0 = ocbase + ocg * 32 + mm * 16 + gid;
        float bv0 = bias[oc0];
        float bv1 = bias[oc0 + 8];
#pragma unroll
        for (int n = 0; n < 8; ++n) {
            int w0 = n * 8 + tig * 2;
            float* p0 = out + (((size_t)b * EMB + ch_off + oc0) * HH + h) * WW + w0;
            float* p1 = p0 + (size_t)8 * HW;
            *reinterpret_cast<float2*>(p0) = make_float2(d[mm][n][0] + bv0, d[mm][n][1] + bv0);
            *reinterpret_cast<float2*>(p1) = make_float2(d[mm][n][2] + bv1, d[mm][n][3] + bv1);
        }
    }
}

// ---------------------------------------------------------------------------
// Global avg + max pool per (b, e).
// ---------------------------------------------------------------------------
__global__ __launch_bounds__(256)
void pool_kernel(const float* __restrict__ fused,
                 float* __restrict__ avg_out, float* __restrict__ max_out)
{
    const int e = blockIdx.x;
    const int b = blockIdx.y;
    const int t = threadIdx.x;

    const float4* p = reinterpret_cast<const float4*>(fused + ((size_t)b * EMB + e) * HW);

    float s = 0.f, m = -INFINITY;
#pragma unroll
    for (int i = 0; i < 4; ++i) {
        float4 v = p[t + i * 256];
        s += v.x + v.y + v.z + v.w;
        m = fmaxf(m, fmaxf(fmaxf(v.x, v.y), fmaxf(v.z, v.w)));
    }

    __shared__ float ss[256], sm[256];
    ss[t] = s; sm[t] = m;
    __syncthreads();
    for (int o = 128; o > 0; o >>= 1) {
        if (t < o) { ss[t] += ss[t + o]; sm[t] = fmaxf(sm[t], sm[t + o]); }
        __syncthreads();
    }
    if (t == 0) {
        avg_out[b * EMB + e] = ss[0] * (1.f / (float)HW);
        max_out[b * EMB + e] = sm[0];
    }
}

// ---------------------------------------------------------------------------
// CBAM MLP + sigmoid.
// ---------------------------------------------------------------------------
__global__ __launch_bounds__(EMB)
void attn_kernel(const float* __restrict__ avg_in, const float* __restrict__ max_in,
                 const float* __restrict__ w1, const float* __restrict__ w2,
                 float* __restrict__ attn)
{
    const int b = blockIdx.x;
    const int t = threadIdx.x;

    __shared__ float s_avg[EMB], s_max[EMB];
    __shared__ float s_h[HID];
    __shared__ float s_ha[HID], s_hm[HID];

    s_avg[t] = avg_in[b * EMB + t];
    s_max[t] = max_in[b * EMB + t];
    __syncthreads();

    if (t < HID) {
        float a = 0.f;
        const float* w1r = w1 + t * EMB;
        for (int e = 0; e < EMB; ++e) a = fmaf(s_avg[e], w1r[e], a);
        s_ha[t] = fmaxf(a, 0.f);
    } else if (t >= 32 && t < 32 + HID) {
        int j = t - 32;
        float a = 0.f;
        const float* w1r = w1 + j * EMB;
        for (int e = 0; e < EMB; ++e) a = fmaf(s_max[e], w1r[e], a);
        s_hm[j] = fmaxf(a, 0.f);
    }
    __syncthreads();
    if (t < HID) s_h[t] = s_ha[t] + s_hm[t];
    __syncthreads();

    float v = 0.f;
    const float* w2r = w2 + t * HID;
#pragma unroll
    for (int j = 0; j < HID; ++j) v = fmaf(s_h[j], w2r[j], v);
    attn[b * EMB + t] = 1.f / (1.f + expf(-v));
}

// ---------------------------------------------------------------------------
// 1x1 fusion conv as tf32 mma GEMM, attn fused into B load.
// ---------------------------------------------------------------------------
#define XSTR 152
__global__ __launch_bounds__(256, 1)
void fusion_mma_kernel(const float* __restrict__ fused, const float* __restrict__ attn,
                       const float* __restrict__ wf, const float* __restrict__ fb,
                       float* __restrict__ out)
{
    __shared__ unsigned s_x[16 * XSTR];
    __shared__ unsigned s_w[128 * 20];

    const int obase = blockIdx.x * 128;
    const int hw0   = blockIdx.y * 128;
    const int b     = blockIdx.z;
    const int t     = threadIdx.x;
    const int warp  = t >> 5;
    const int lane  = t & 31;
    const int gid   = lane >> 2;
    const int tig   = lane & 3;
    const int ocb   = warp * 16;

    float d[16][4];
#pragma unroll
    for (int i = 0; i < 16; ++i)
#pragma unroll
        for (int j = 0; j < 4; ++j) d[i][j] = 0.f;

    int x_cc[2], x_hw[2];
#pragma unroll
    for (int j = 0; j < 2; ++j) {
        int i4 = t + j * 256;
        x_cc[j] = i4 >> 5;
        x_hw[j] = (i4 & 31) * 4;
    }
    int w_oc[8], w_cc[8];
#pragma unroll
    for (int j = 0; j < 8; ++j) {
        int i = t + j * 256;
        w_oc[j] = i >> 4;
        w_cc[j] = i & 15;
    }

    const float* xb = fused + (size_t)b * EMB * HW + hw0;
    const float* ab = attn + b * EMB;

    float4 xv[2];  float wv[8];  float av[2];
#pragma unroll
    for (int j = 0; j < 2; ++j) {
        xv[j] = *reinterpret_cast<const float4*>(xb + (size_t)x_cc[j] * HW + x_hw[j]);
        av[j] = ab[x_cc[j]];
    }
#pragma unroll
    for (int j = 0; j < 8; ++j)
        wv[j] = wf[(size_t)(obase + w_oc[j]) * EMB + w_cc[j]];

    for (int cb = 0; cb < EMB; cb += 16) {
        __syncthreads();
#pragma unroll
        for (int j = 0; j < 2; ++j) {
            unsigned* p = &s_x[x_cc[j] * XSTR + x_hw[j]];
            p[0] = f2tf32(xv[j].x * av[j]);
            p[1] = f2tf32(xv[j].y * av[j]);
            p[2] = f2tf32(xv[j].z * av[j]);
            p[3] = f2tf32(xv[j].w * av[j]);
        }
#pragma unroll
        for (int j = 0; j < 8; ++j)
            s_w[w_oc[j] * 20 + w_cc[j]] = f2tf32(wv[j]);

        float4 xv2[2]; float wv2[8]; float av2[2];
        const int cn = cb + 16;
        if (cn < EMB) {
#pragma unroll
            for (int j = 0; j < 2; ++j) {
                xv2[j] = *reinterpret_cast<const float4*>(
                    xb + (size_t)(cn + x_cc[j]) * HW + x_hw[j]);
                av2[j] = ab[cn + x_cc[j]];
            }
#pragma unroll
            for (int j = 0; j < 8; ++j)
                wv2[j] = wf[(size_t)(obase + w_oc[j]) * EMB + cn + w_cc[j]];
        }
        __syncthreads();

#pragma unroll
        for (int ks = 0; ks < 2; ++ks) {
            const int kb = ks * 8;
            unsigned a0 = s_w[(ocb + gid)     * 20 + kb + tig];
            unsigned a1 = s_w[(ocb + gid + 8) * 20 + kb + tig];
            unsigned a2 = s_w[(ocb + gid)     * 20 + kb + tig + 4];
            unsigned a3 = s_w[(ocb + gid + 8) * 20 + kb + tig + 4];
            const int base_b = (kb + tig) * XSTR + gid;
#pragma unroll
            for (int t16 = 0; t16 < 16; ++t16) {
                const int off = base_b + t16 * 8;
                unsigned b0 = s_x[off];
                unsigned b1 = s_x[off + 4 * XSTR];
                mma_tf32(d[t16][0], d[t16][1], d[t16][2], d[t16][3],
                         a0, a1, a2, a3, b0, b1);
            }
        }
#pragma unroll
        for (int j = 0; j < 2; ++j) { xv[j] = xv2[j]; av[j] = av2[j]; }
#pragma unroll
        for (int j = 0; j < 8; ++j) wv[j] = wv2[j];
    }

    const int o0 = obase + ocb + gid;
    const float bv0 = fb[o0];
    const float bv1 = fb[o0 + 8];
#pragma unroll
    for (int t16 = 0; t16 < 16; ++t16) {
        const int n0 = t16 * 8 + tig * 2;
        float* p0 = out + ((size_t)b * EMB + o0)     * HW + hw0 + n0;
        float* p1 = out + ((size_t)b * EMB + o0 + 8) * HW + hw0 + n0;
        *reinterpret_cast<float2*>(p0) = make_float2(d[t16][0] + bv0, d[t16][1] + bv0);
        *reinterpret_cast<float2*>(p1) = make_float2(d[t16][2] + bv1, d[t16][3] + bv1);
    }
}

// ---------------------------------------------------------------------------
// Transpose [B,E,HW] -> [B,HW,E] + LayerNorm over E.
// ---------------------------------------------------------------------------
__global__ __launch_bounds__(256)
void ln_kernel(const float* __restrict__ g, const float* __restrict__ gamma,
               const float* __restrict__ beta, float* __restrict__ out)
{
    __shared__ float s[EMB * 17];

    const int hw0 = blockIdx.x * 16;
    const int b   = blockIdx.y;
    const int t   = threadIdx.x;

    const float* gb = g + (size_t)b * EMB * HW + hw0;
    for (int i = t; i < EMB * 16; i += 256) {
        int e   = i >> 4;
        int tok = i & 15;
        s[e * 17 + tok] = gb[(size_t)e * HW + tok];
    }
    __syncthreads();

    const int warp = t >> 5;
    const int lane = t & 31;

#pragma unroll
    for (int tt = 0; tt < 2; ++tt) {
        int tok = warp * 2 + tt;
        float vals[12];
        float sum = 0.f, sq = 0.f;
#pragma unroll
        for (int k = 0; k < 12; ++k) {
            float v = s[(lane + 32 * k) * 17 + tok];
            vals[k] = v;
            sum += v;
            sq  = fmaf(v, v, sq);
        }
#pragma unroll
        for (int o = 16; o > 0; o >>= 1) {
            sum += __shfl_xor_sync(0xFFFFFFFFu, sum, o);
            sq  += __shfl_xor_sync(0xFFFFFFFFu, sq,  o);
        }
        float mu  = sum * (1.f / (float)EMB);
        float var = sq * (1.f / (float)EMB) - mu * mu;
        float rstd = rsqrtf(var + 1e-5f);

        float* dst = out + ((size_t)b * HW + hw0 + tok) * EMB;
#pragma unroll
        for (int k = 0; k < 12; ++k) {
            int e = lane + 32 * k;
            dst[e] = (vals[k] - mu) * rstd * gamma[e] + beta[e];
        }
    }
}

// ---------------------------------------------------------------------------
// Launcher.
// ---------------------------------------------------------------------------
extern "C" void kernel_launch(void* const* d_in, const int* in_sizes, int n_in,
                              void* d_out, int out_size)
{
    const float* x   = (const float*)d_in[0];
    const float* w3  = (const float*)d_in[1];
    const float* b3  = (const float*)d_in[2];
    const float* w5  = (const float*)d_in[3];
    const float* b5  = (const float*)d_in[4];
    const float* w7  = (const float*)d_in[5];
    const float* b7  = (const float*)d_in[6];
    const float* cw1 = (const float*)d_in[7];
    const float* cw2 = (const float*)d_in[8];
    const float* fw  = (const float*)d_in[9];
    const float* fbi = (const float*)d_in[10];
    const float* lng = (const float*)d_in[11];
    const float* lnb = (const float*)d_in[12];
    float* out = (float*)d_out;

    float* fused; cudaGetSymbolAddress((void**)&fused, g_fused);
    float* gout;  cudaGetSymbolAddress((void**)&gout,  g_gout);
    float* gavg;  cudaGetSymbolAddress((void**)&gavg,  g_avg);
    float* gmax;  cudaGetSymbolAddress((void**)&gmax,  g_max);
    float* gattn; cudaGetSymbolAddress((void**)&gattn, g_attn);
    __half* xh;  cudaGetSymbolAddress((void**)&xh,  g_xh);
    __half* wh3; cudaGetSymbolAddress((void**)&wh3, g_wh3);
    __half* wh5; cudaGetSymbolAddress((void**)&wh5, g_wh5);
    __half* wh7; cudaGetSymbolAddress((void**)&wh7, g_wh7);

    // pre-pass conversions
    prep_xh_kernel<<<dim3(HW / 128, CB16, BATCH), 256>>>(x, xh);
    prep_wh_kernel<<<(9  * EB * CIN + 255) / 256, 256>>>(w3, wh3, 9);
    prep_wh_kernel<<<(25 * EB * CIN + 255) / 256, 256>>>(w5, wh5, 25);
    prep_wh_kernel<<<(49 * EB * CIN + 255) / 256, 256>>>(w7, wh7, 49);

    // convs: K3/K5 -> 128oc x 2rows; K7 -> 64oc x 4rows
    conv_f16_kernel<3, 2, 128><<<dim3(HH / 2, BATCH, 1), 256>>>(xh, wh3, b3, fused, 0);
    conv_f16_kernel<5, 2, 128><<<dim3(HH / 2, BATCH, 1), 256>>>(xh, wh5, b5, fused, EB);
    conv_f16_kernel<7, 4, 64><<<dim3(HH / 4, BATCH, 2), 256>>>(xh, wh7, b7, fused, 2 * EB);

    pool_kernel<<<dim3(EMB, BATCH), 256>>>(fused, gavg, gmax);
    attn_kernel<<<BATCH, EMB>>>(gavg, gmax, cw1, cw2, gattn);

    fusion_mma_kernel<<<dim3(EMB / 128, HW / 128, BATCH), 256>>>(fused, gattn, fw, fbi, gout);

    ln_kernel<<<dim3(HW / 16, BATCH), 256>>>(gout, lng, lnb, out);
}

// round 7
// speedup vs baseline: 13.0489x; 1.0586x over previous
#include <cuda_runtime.h>
#include <cuda_fp16.h>
#include <cuda_bf16.h>
#include <math.h>

// Problem constants
#define BATCH 32
#define CIN   128
#define CB16  (CIN/16)
#define HH    64
#define WW    64
#define HW    (HH*WW)
#define EMB   384
#define ECB   (EMB/16)     // 24
#define EB    128
#define HID   24

// ---------------- scratch (device globals) ----------------------------------
__device__ float  g_fused[(size_t)BATCH * EMB * HW];
__device__ float  g_gout [(size_t)BATCH * EMB * HW];
__device__ float  g_avg  [BATCH * EMB];
__device__ float  g_max  [BATCH * EMB];
__device__ float  g_attn [BATCH * EMB];
__device__ __half g_xh   [(size_t)BATCH * CB16 * HW * 16];  // [b][cb][h][w][c16]
__device__ __half g_fh   [(size_t)BATCH * ECB * HW * 16];   // fused*attn fp16 [b][cb][hw][c16]
__device__ __half g_wh3  [9  * EB * CIN];                   // [tap][oc][c]
__device__ __half g_wh5  [25 * EB * CIN];
__device__ __half g_wh7  [49 * EB * CIN];
__device__ __half g_wfh  [EMB * EMB];                       // fusion weights fp16 [o][c]

// ---- helpers ---------------------------------------------------------------
__device__ __forceinline__ void mma_f16(float& d0, float& d1, float& d2, float& d3,
                                        unsigned a0, unsigned a1, unsigned a2, unsigned a3,
                                        unsigned b0, unsigned b1) {
    asm("mma.sync.aligned.m16n8k16.row.col.f32.f16.f16.f32 "
        "{%0,%1,%2,%3}, {%4,%5,%6,%7}, {%8,%9}, {%0,%1,%2,%3};"
        : "+f"(d0), "+f"(d1), "+f"(d2), "+f"(d3)
        : "r"(a0), "r"(a1), "r"(a2), "r"(a3), "r"(b0), "r"(b1));
}
__device__ __forceinline__ void ldsm_x4(unsigned& r0, unsigned& r1, unsigned& r2, unsigned& r3,
                                        unsigned addr) {
    asm volatile("ldmatrix.sync.aligned.m8n8.x4.shared.b16 {%0,%1,%2,%3}, [%4];"
                 : "=r"(r0), "=r"(r1), "=r"(r2), "=r"(r3) : "r"(addr));
}

// ---------------------------------------------------------------------------
// Pre-pass: x [B][C][H][W] fp32 -> g_xh [b][cb][h][w][c16] fp16
// ---------------------------------------------------------------------------
__global__ __launch_bounds__(256)
void prep_xh_kernel(const float* __restrict__ x, __half* __restrict__ xh)
{
    __shared__ __half s[16][129];
    const int hw0 = blockIdx.x * 128;
    const int cb  = blockIdx.y;
    const int b   = blockIdx.z;
    const int t   = threadIdx.x;

#pragma unroll
    for (int p = 0; p < 8; ++p) {
        int ci = p * 2 + (t >> 7);
        int j  = t & 127;
        s[ci][j] = __float2half(x[((size_t)(b * CIN + cb * 16 + ci)) * HW + hw0 + j]);
    }
    __syncthreads();

    int j    = t >> 1;
    int csel = t & 1;
    __half tmp[8];
#pragma unroll
    for (int k = 0; k < 8; ++k) tmp[k] = s[csel * 8 + k][j];
    *reinterpret_cast<uint4*>(&xh[(((size_t)(b * CB16 + cb)) * HW + hw0 + j) * 16 + csel * 8]) =
        *reinterpret_cast<uint4*>(tmp);
}

// Pre-pass: fused*attn fp32 -> g_fh [b][cb][hw][c16] fp16
__global__ __launch_bounds__(256)
void prep_fh_kernel(const float* __restrict__ fused, const float* __restrict__ attn,
                    __half* __restrict__ fh)
{
    __shared__ __half s[16][129];
    const int hw0 = blockIdx.x * 128;
    const int cb  = blockIdx.y;
    const int b   = blockIdx.z;
    const int t   = threadIdx.x;

#pragma unroll
    for (int p = 0; p < 8; ++p) {
        int ci = p * 2 + (t >> 7);
        int j  = t & 127;
        int c  = cb * 16 + ci;
        s[ci][j] = __float2half(fused[((size_t)(b * EMB + c)) * HW + hw0 + j] *
                                attn[b * EMB + c]);
    }
    __syncthreads();

    int j    = t >> 1;
    int csel = t & 1;
    __half tmp[8];
#pragma unroll
    for (int k = 0; k < 8; ++k) tmp[k] = s[csel * 8 + k][j];
    *reinterpret_cast<uint4*>(&fh[(((size_t)(b * ECB + cb)) * HW + hw0 + j) * 16 + csel * 8]) =
        *reinterpret_cast<uint4*>(tmp);
}

// Pre-pass: w [oc][c][kk] fp32 -> wh [kk][oc][c] fp16
__global__ __launch_bounds__(256)
void prep_wh_kernel(const float* __restrict__ w, __half* __restrict__ wh, int kkN)
{
    int idx = blockIdx.x * 256 + threadIdx.x;
    int total = kkN * EB * CIN;
    if (idx < total) {
        int c  = idx & 127;
        int oc = (idx >> 7) & 127;
        int kk = idx >> 14;
        wh[idx] = __float2half(w[((size_t)oc * CIN + c) * kkN + kk]);
    }
}

// Pre-pass: fusion weights fp32 -> fp16 (same [o][c] layout)
__global__ __launch_bounds__(256)
void prep_wfh_kernel(const float* __restrict__ w, __half* __restrict__ wh)
{
    int idx = blockIdx.x * 256 + threadIdx.x;
    if (idx < EMB * EMB) wh[idx] = __float2half(w[idx]);
}

// ---------------------------------------------------------------------------
// Conv via fp16 mma m16n8k16 + ldmatrix.
//  - single __syncthreads per kh-group (double-buffered s_w by stage parity,
//    s_in by c-block parity)
//  - B fragments loaded pairwise with ldmatrix.x4 (4 per tap instead of 8 x2)
//  - weights register-prefetched one kh-group ahead
// ---------------------------------------------------------------------------
template<int K, int ROWS, int OCB>
__global__ __launch_bounds__(256)
void conv_f16_kernel(const __half* __restrict__ xh, const __half* __restrict__ wh,
                     const float* __restrict__ bias, float* __restrict__ out, int ch_off)
{
    constexpr int HALO    = K / 2;
    constexpr int WIN     = WW + K - 1;
    constexpr int IN_ROWS = ROWS + K - 1;
    constexpr int NOG     = OCB / 32;
    constexpr int NSG     = 8 / NOG;       // == ROWS
    constexpr int NITEM   = K * OCB;       // weight granules per kh-group
    constexpr int NPF     = (NITEM + 255) / 256;
    constexpr int NCHUNK  = IN_ROWS * WIN * 2;
    constexpr int SINB    = IN_ROWS * WIN * 32;   // bytes per input buffer
    constexpr int SWB     = K * OCB * 32;         // bytes per weight buffer

    extern __shared__ __align__(128) unsigned char dsm[];
    unsigned char* sin_raw[2] = { dsm, dsm + SINB };
    unsigned char* sw_raw [2] = { dsm + 2 * SINB, dsm + 2 * SINB + SWB };
    const unsigned sin_base[2] = { (unsigned)__cvta_generic_to_shared(sin_raw[0]),
                                   (unsigned)__cvta_generic_to_shared(sin_raw[1]) };
    const unsigned sw_base [2] = { (unsigned)__cvta_generic_to_shared(sw_raw[0]),
                                   (unsigned)__cvta_generic_to_shared(sw_raw[1]) };

    const int h0     = blockIdx.x * ROWS;
    const int b      = blockIdx.y;
    const int ocbase = blockIdx.z * OCB;
    const int t      = threadIdx.x;
    const int warp   = t >> 5;
    const int lane   = t & 31;
    const int gid    = lane >> 2;
    const int tig    = lane & 3;
    const int ocg    = warp / NSG;
    const int rw     = warp % NSG;

    float d[2][8][4];
#pragma unroll
    for (int mm = 0; mm < 2; ++mm)
#pragma unroll
        for (int n = 0; n < 8; ++n)
#pragma unroll
            for (int j = 0; j < 4; ++j) d[mm][n][j] = 0.f;

    // fragment lane-address components
    const int laneA  = lane & 15;
    const int cselA  = (lane >> 4) & 1;
    const int laneB4 = (lane & 7) | (((lane >> 4) & 1) << 3);  // row within 16-pair
    const int cselB4 = (lane >> 3) & 1;

    uint4 wra[NPF], wrb[NPF];

    // prologue: prefetch kh-group 0, c-block 0
#pragma unroll
    for (int j = 0; j < NPF; ++j) {
        int it = t + j * 256;
        if (it < NITEM) {
            int tap = it / OCB, oc = it - tap * OCB;
            const uint4* src = reinterpret_cast<const uint4*>(
                wh + ((size_t)tap * EB + ocbase + oc) * CIN);
            wra[j] = src[0];
            wrb[j] = src[1];
        }
    }

    for (int cb = 0; cb < CB16; ++cb) {
        // ---- stage inputs into buffer (cb&1): [n = r*WIN+col][c16], swizzled --
        const __half* xc = xh + ((size_t)(b * CB16 + cb)) * HW * 16;
        unsigned char* sin_w = sin_raw[cb & 1];
        for (int q = t; q < NCHUNK; q += 256) {
            int n = q >> 1, cs = q & 1;
            int r = n / WIN, col = n - r * WIN;
            int gr = h0 + r - HALO, gw = col - HALO;
            uint4 v = make_uint4(0u, 0u, 0u, 0u);
            if ((unsigned)gr < HH && (unsigned)gw < WW)
                v = *reinterpret_cast<const uint4*>(xc + ((size_t)gr * WW + gw) * 16 + cs * 8);
            unsigned off = (unsigned)(n * 32 + cs * 16) ^ ((n & 4) << 2);
            *reinterpret_cast<uint4*>(sin_w + off) = v;
        }
        const unsigned sinb = sin_base[cb & 1];

#pragma unroll
        for (int g = 0; g < K; ++g) {
            const int s = cb * K + g;
            unsigned char* sww = sw_raw[s & 1];
            const unsigned swb = sw_base[s & 1];
            // store this group's prefetched weights
#pragma unroll
            for (int j = 0; j < NPF; ++j) {
                int it = t + j * 256;
                if (it < NITEM) {
                    unsigned sw2 = (unsigned)((it & 4) << 2);
                    *reinterpret_cast<uint4*>(sww + (((unsigned)(it * 32))      ^ sw2)) = wra[j];
                    *reinterpret_cast<uint4*>(sww + (((unsigned)(it * 32 + 16)) ^ sw2)) = wrb[j];
                }
            }
            // prefetch next group
            {
                int gn = g + 1, cn = cb;
                if (gn == K) { gn = 0; cn = cb + 1; }
                if (cn < CB16) {
#pragma unroll
                    for (int j = 0; j < NPF; ++j) {
                        int it = t + j * 256;
                        if (it < NITEM) {
                            int tap = it / OCB, oc = it - tap * OCB;
                            const uint4* src = reinterpret_cast<const uint4*>(
                                wh + ((size_t)(gn * K + tap) * EB + ocbase + oc) * CIN + cn * 16);
                            wra[j] = src[0];
                            wrb[j] = src[1];
                        }
                    }
                }
            }
            __syncthreads();   // staged tiles visible; also separates buffer reuse

            const int rowbase = (rw + g) * WIN;
#pragma unroll
            for (int kw = 0; kw < K; ++kw) {
                unsigned a[2][4];
#pragma unroll
                for (int mm = 0; mm < 2; ++mm) {
                    int gA = kw * OCB + ocg * 32 + mm * 16 + laneA;
                    unsigned offA = (unsigned)(gA * 32 + cselA * 16) ^ ((gA & 4) << 2);
                    ldsm_x4(a[mm][0], a[mm][1], a[mm][2], a[mm][3], swb + offA);
                }
#pragma unroll
                for (int ntp = 0; ntp < 4; ++ntp) {
                    int gB = rowbase + ntp * 16 + laneB4 + kw;
                    unsigned offB = (unsigned)(gB * 32 + cselB4 * 16) ^ ((gB & 4) << 2);
                    unsigned b0, b1, b2, b3;
                    ldsm_x4(b0, b1, b2, b3, sinb + offB);
                    const int n0 = ntp * 2;
                    mma_f16(d[0][n0][0], d[0][n0][1], d[0][n0][2], d[0][n0][3],
                            a[0][0], a[0][1], a[0][2], a[0][3], b0, b1);
                    mma_f16(d[1][n0][0], d[1][n0][1], d[1][n0][2], d[1][n0][3],
                            a[1][0], a[1][1], a[1][2], a[1][3], b0, b1);
                    mma_f16(d[0][n0+1][0], d[0][n0+1][1], d[0][n0+1][2], d[0][n0+1][3],
                            a[0][0], a[0][1], a[0][2], a[0][3], b2, b3);
                    mma_f16(d[1][n0+1][0], d[1][n0+1][1], d[1][n0+1][2], d[1][n0+1][3],
                            a[1][0], a[1][1], a[1][2], a[1][3], b2, b3);
                }
            }
        }
    }

    // ---- epilogue ----
    const int h = h0 + rw;
#pragma unroll
    for (int mm = 0; mm < 2; ++mm) {
        int oc0 = ocbase + ocg * 32 + mm * 16 + gid;
        float bv0 = bias[oc0];
        float bv1 = bias[oc0 + 8];
#pragma unroll
        for (int n = 0; n < 8; ++n) {
            int w0 = n * 8 + tig * 2;
            float* p0 = out + (((size_t)b * EMB + ch_off + oc0) * HH + h) * WW + w0;
            float* p1 = p0 + (size_t)8 * HW;
            *reinterpret_cast<float2*>(p0) = make_float2(d[mm][n][0] + bv0, d[mm][n][1] + bv0);
            *reinterpret_cast<float2*>(p1) = make_float2(d[mm][n][2] + bv1, d[mm][n][3] + bv1);
        }
    }
}

// ---------------------------------------------------------------------------
// Fusion 1x1 conv as fp16 GEMM (same machinery, K=1, no halo).
// Block: 128 o x 128 hw. Warps: ocg = warp>>1 (4 x 32 oc), hwg = warp&1 (2 x 64).
// ---------------------------------------------------------------------------
__global__ __launch_bounds__(256)
void gemm_f16_kernel(const __half* __restrict__ fh, const __half* __restrict__ wfh,
                     const float* __restrict__ fb, float* __restrict__ out)
{
    __shared__ __align__(128) unsigned char sA[2][4096];
    __shared__ __align__(128) unsigned char sB[2][4096];

    const int obase = blockIdx.x * 128;
    const int hw0   = blockIdx.y * 128;
    const int b     = blockIdx.z;
    const int t     = threadIdx.x;
    const int warp  = t >> 5;
    const int lane  = t & 31;
    const int gid   = lane >> 2;
    const int tig   = lane & 3;
    const int ocg   = warp >> 1;
    const int hwg   = warp & 1;

    const unsigned sAb[2] = { (unsigned)__cvta_generic_to_shared(sA[0]),
                              (unsigned)__cvta_generic_to_shared(sA[1]) };
    const unsigned sBb[2] = { (unsigned)__cvta_generic_to_shared(sB[0]),
                              (unsigned)__cvta_generic_to_shared(sB[1]) };

    const int laneA  = lane & 15;
    const int cselA  = (lane >> 4) & 1;
    const int laneB4 = (lane & 7) | (((lane >> 4) & 1) << 3);
    const int cselB4 = (lane >> 3) & 1;

    float d[2][8][4];
#pragma unroll
    for (int mm = 0; mm < 2; ++mm)
#pragma unroll
        for (int n = 0; n < 8; ++n)
#pragma unroll
            for (int j = 0; j < 4; ++j) d[mm][n][j] = 0.f;

    // per-thread staging granule: row = t>>1, csel = t&1 (one uint4 each)
    const int grow = t >> 1;
    const int gcs  = t & 1;
    const unsigned stoff = (unsigned)(grow * 32 + gcs * 16) ^ ((grow & 4) << 2);

    const __half* Asrc = wfh + (size_t)(obase + grow) * EMB + gcs * 8;
    const __half* Bsrc = fh + ((size_t)b * ECB * HW + hw0 + grow) * 16 + gcs * 8;

    uint4 av = *reinterpret_cast<const uint4*>(Asrc);
    uint4 bv = *reinterpret_cast<const uint4*>(Bsrc);

    for (int cb = 0; cb < ECB; ++cb) {
        const int p = cb & 1;
        *reinterpret_cast<uint4*>(sA[p] + stoff) = av;
        *reinterpret_cast<uint4*>(sB[p] + stoff) = bv;
        if (cb + 1 < ECB) {
            av = *reinterpret_cast<const uint4*>(Asrc + (cb + 1) * 16);
            bv = *reinterpret_cast<const uint4*>(Bsrc + (size_t)(cb + 1) * HW * 16);
        }
        __syncthreads();

        unsigned a[2][4];
#pragma unroll
        for (int mm = 0; mm < 2; ++mm) {
            int gA = ocg * 32 + mm * 16 + laneA;
            unsigned offA = (unsigned)(gA * 32 + cselA * 16) ^ ((gA & 4) << 2);
            ldsm_x4(a[mm][0], a[mm][1], a[mm][2], a[mm][3], sAb[p] + offA);
        }
        const int rowbase = hwg * 64;
#pragma unroll
        for (int ntp = 0; ntp < 4; ++ntp) {
            int gB = rowbase + ntp * 16 + laneB4;
            unsigned offB = (unsigned)(gB * 32 + cselB4 * 16) ^ ((gB & 4) << 2);
            unsigned b0, b1, b2, b3;
            ldsm_x4(b0, b1, b2, b3, sBb[p] + offB);
            const int n0 = ntp * 2;
            mma_f16(d[0][n0][0], d[0][n0][1], d[0][n0][2], d[0][n0][3],
                    a[0][0], a[0][1], a[0][2], a[0][3], b0, b1);
            mma_f16(d[1][n0][0], d[1][n0][1], d[1][n0][2], d[1][n0][3],
                    a[1][0], a[1][1], a[1][2], a[1][3], b0, b1);
            mma_f16(d[0][n0+1][0], d[0][n0+1][1], d[0][n0+1][2], d[0][n0+1][3],
                    a[0][0], a[0][1], a[0][2], a[0][3], b2, b3);
            mma_f16(d[1][n0+1][0], d[1][n0+1][1], d[1][n0+1][2], d[1][n0+1][3],
                    a[1][0], a[1][1], a[1][2], a[1][3], b2, b3);
        }
    }

    // epilogue
#pragma unroll
    for (int mm = 0; mm < 2; ++mm) {
        int oc0 = obase + ocg * 32 + mm * 16 + gid;
        float bv0 = fb[oc0];
        float bv1 = fb[oc0 + 8];
#pragma unroll
        for (int n = 0; n < 8; ++n) {
            int col = hw0 + hwg * 64 + n * 8 + tig * 2;
            float* p0 = out + ((size_t)b * EMB + oc0) * HW + col;
            float* p1 = p0 + (size_t)8 * HW;
            *reinterpret_cast<float2*>(p0) = make_float2(d[mm][n][0] + bv0, d[mm][n][1] + bv0);
            *reinterpret_cast<float2*>(p1) = make_float2(d[mm][n][2] + bv1, d[mm][n][3] + bv1);
        }
    }
}

// ---------------------------------------------------------------------------
// Global avg + max pool per (b, e).
// ---------------------------------------------------------------------------
__global__ __launch_bounds__(256)
void pool_kernel(const float* __restrict__ fused,
                 float* __restrict__ avg_out, float* __restrict__ max_out)
{
    const int e = blockIdx.x;
    const int b = blockIdx.y;
    const int t = threadIdx.x;

    const float4* p = reinterpret_cast<const float4*>(fused + ((size_t)b * EMB + e) * HW);

    float s = 0.f, m = -INFINITY;
#pragma unroll
    for (int i = 0; i < 4; ++i) {
        float4 v = p[t + i * 256];
        s += v.x + v.y + v.z + v.w;
        m = fmaxf(m, fmaxf(fmaxf(v.x, v.y), fmaxf(v.z, v.w)));
    }

    __shared__ float ss[256], sm[256];
    ss[t] = s; sm[t] = m;
    __syncthreads();
    for (int o = 128; o > 0; o >>= 1) {
        if (t < o) { ss[t] += ss[t + o]; sm[t] = fmaxf(sm[t], sm[t + o]); }
        __syncthreads();
    }
    if (t == 0) {
        avg_out[b * EMB + e] = ss[0] * (1.f / (float)HW);
        max_out[b * EMB + e] = sm[0];
    }
}

// ---------------------------------------------------------------------------
// CBAM MLP + sigmoid.
// ---------------------------------------------------------------------------
__global__ __launch_bounds__(EMB)
void attn_kernel(const float* __restrict__ avg_in, const float* __restrict__ max_in,
                 const float* __restrict__ w1, const float* __restrict__ w2,
                 float* __restrict__ attn)
{
    const int b = blockIdx.x;
    const int t = threadIdx.x;

    __shared__ float s_avg[EMB], s_max[EMB];
    __shared__ float s_h[HID];
    __shared__ float s_ha[HID], s_hm[HID];

    s_avg[t] = avg_in[b * EMB + t];
    s_max[t] = max_in[b * EMB + t];
    __syncthreads();

    if (t < HID) {
        float a = 0.f;
        const float* w1r = w1 + t * EMB;
        for (int e = 0; e < EMB; ++e) a = fmaf(s_avg[e], w1r[e], a);
        s_ha[t] = fmaxf(a, 0.f);
    } else if (t >= 32 && t < 32 + HID) {
        int j = t - 32;
        float a = 0.f;
        const float* w1r = w1 + j * EMB;
        for (int e = 0; e < EMB; ++e) a = fmaf(s_max[e], w1r[e], a);
        s_hm[j] = fmaxf(a, 0.f);
    }
    __syncthreads();
    if (t < HID) s_h[t] = s_ha[t] + s_hm[t];
    __syncthreads();

    float v = 0.f;
    const float* w2r = w2 + t * HID;
#pragma unroll
    for (int j = 0; j < HID; ++j) v = fmaf(s_h[j], w2r[j], v);
    attn[b * EMB + t] = 1.f / (1.f + expf(-v));
}

// ---------------------------------------------------------------------------
// Transpose [B,E,HW] -> [B,HW,E] + LayerNorm over E.
// ---------------------------------------------------------------------------
__global__ __launch_bounds__(256)
void ln_kernel(const float* __restrict__ g, const float* __restrict__ gamma,
               const float* __restrict__ beta, float* __restrict__ out)
{
    __shared__ float s[EMB * 17];

    const int hw0 = blockIdx.x * 16;
    const int b   = blockIdx.y;
    const int t   = threadIdx.x;

    const float* gb = g + (size_t)b * EMB * HW + hw0;
    for (int i = t; i < EMB * 16; i += 256) {
        int e   = i >> 4;
        int tok = i & 15;
        s[e * 17 + tok] = gb[(size_t)e * HW + tok];
    }
    __syncthreads();

    const int warp = t >> 5;
    const int lane = t & 31;

#pragma unroll
    for (int tt = 0; tt < 2; ++tt) {
        int tok = warp * 2 + tt;
        float vals[12];
        float sum = 0.f, sq = 0.f;
#pragma unroll
        for (int k = 0; k < 12; ++k) {
            float v = s[(lane + 32 * k) * 17 + tok];
            vals[k] = v;
            sum += v;
            sq  = fmaf(v, v, sq);
        }
#pragma unroll
        for (int o = 16; o > 0; o >>= 1) {
            sum += __shfl_xor_sync(0xFFFFFFFFu, sum, o);
            sq  += __shfl_xor_sync(0xFFFFFFFFu, sq,  o);
        }
        float mu  = sum * (1.f / (float)EMB);
        float var = sq * (1.f / (float)EMB) - mu * mu;
        float rstd = rsqrtf(var + 1e-5f);

        float* dst = out + ((size_t)b * HW + hw0 + tok) * EMB;
#pragma unroll
        for (int k = 0; k < 12; ++k) {
            int e = lane + 32 * k;
            dst[e] = (vals[k] - mu) * rstd * gamma[e] + beta[e];
        }
    }
}

// ---------------------------------------------------------------------------
// Launcher.
// ---------------------------------------------------------------------------
extern "C" void kernel_launch(void* const* d_in, const int* in_sizes, int n_in,
                              void* d_out, int out_size)
{
    const float* x   = (const float*)d_in[0];
    const float* w3  = (const float*)d_in[1];
    const float* b3  = (const float*)d_in[2];
    const float* w5  = (const float*)d_in[3];
    const float* b5  = (const float*)d_in[4];
    const float* w7  = (const float*)d_in[5];
    const float* b7  = (const float*)d_in[6];
    const float* cw1 = (const float*)d_in[7];
    const float* cw2 = (const float*)d_in[8];
    const float* fw  = (const float*)d_in[9];
    const float* fbi = (const float*)d_in[10];
    const float* lng = (const float*)d_in[11];
    const float* lnb = (const float*)d_in[12];
    float* out = (float*)d_out;

    float* fused; cudaGetSymbolAddress((void**)&fused, g_fused);
    float* gout;  cudaGetSymbolAddress((void**)&gout,  g_gout);
    float* gavg;  cudaGetSymbolAddress((void**)&gavg,  g_avg);
    float* gmax;  cudaGetSymbolAddress((void**)&gmax,  g_max);
    float* gattn; cudaGetSymbolAddress((void**)&gattn, g_attn);
    __half* xh;  cudaGetSymbolAddress((void**)&xh,  g_xh);
    __half* fh;  cudaGetSymbolAddress((void**)&fh,  g_fh);
    __half* wh3; cudaGetSymbolAddress((void**)&wh3, g_wh3);
    __half* wh5; cudaGetSymbolAddress((void**)&wh5, g_wh5);
    __half* wh7; cudaGetSymbolAddress((void**)&wh7, g_wh7);
    __half* wfh; cudaGetSymbolAddress((void**)&wfh, g_wfh);

    // dynamic smem: 2*(input buf) + 2*(weight buf)
    constexpr int SM3 = 2 * (4  * 66 * 32) + 2 * (3 * 128 * 32);   // 41472
    constexpr int SM5 = 2 * (6  * 68 * 32) + 2 * (5 * 128 * 32);   // 67072
    constexpr int SM7 = 2 * (10 * 70 * 32) + 2 * (7 * 64  * 32);   // 73472
    cudaFuncSetAttribute(conv_f16_kernel<3, 2, 128>, cudaFuncAttributeMaxDynamicSharedMemorySize, SM3);
    cudaFuncSetAttribute(conv_f16_kernel<5, 2, 128>, cudaFuncAttributeMaxDynamicSharedMemorySize, SM5);
    cudaFuncSetAttribute(conv_f16_kernel<7, 4, 64>,  cudaFuncAttributeMaxDynamicSharedMemorySize, SM7);

    // pre-pass conversions
    prep_xh_kernel<<<dim3(HW / 128, CB16, BATCH), 256>>>(x, xh);
    prep_wh_kernel<<<(9  * EB * CIN + 255) / 256, 256>>>(w3, wh3, 9);
    prep_wh_kernel<<<(25 * EB * CIN + 255) / 256, 256>>>(w5, wh5, 25);
    prep_wh_kernel<<<(49 * EB * CIN + 255) / 256, 256>>>(w7, wh7, 49);
    prep_wfh_kernel<<<(EMB * EMB + 255) / 256, 256>>>(fw, wfh);

    // convs
    conv_f16_kernel<3, 2, 128><<<dim3(HH / 2, BATCH, 1), 256, SM3>>>(xh, wh3, b3, fused, 0);
    conv_f16_kernel<5, 2, 128><<<dim3(HH / 2, BATCH, 1), 256, SM5>>>(xh, wh5, b5, fused, EB);
    conv_f16_kernel<7, 4, 64><<<dim3(HH / 4, BATCH, 2), 256, SM7>>>(xh, wh7, b7, fused, 2 * EB);

    pool_kernel<<<dim3(EMB, BATCH), 256>>>(fused, gavg, gmax);
    attn_kernel<<<BATCH, EMB>>>(gavg, gmax, cw1, cw2, gattn);

    // fused * attn -> fp16 [b][cb][hw][c16], then fp16 GEMM
    prep_fh_kernel<<<dim3(HW / 128, ECB, BATCH), 256>>>(fused, gattn, fh);
    gemm_f16_kernel<<<dim3(EMB / 128, HW / 128, BATCH), 256>>>(fh, wfh, fbi, gout);

    ln_kernel<<<dim3(HW / 16, BATCH), 256>>>(gout, lng, lnb, out);
}

// round 8
// speedup vs baseline: 17.1074x; 1.3110x over previous
#include <cuda_runtime.h>
#include <cuda_fp16.h>
#include <cuda_bf16.h>
#include <math.h>

// Problem constants
#define BATCH 32
#define CIN   128
#define CB16  (CIN/16)
#define HH    64
#define WW    64
#define HW    (HH*WW)
#define EMB   384
#define ECB   (EMB/16)     // 24
#define EB    128
#define HID   24

// ---------------- scratch (device globals) ----------------------------------
__device__ float  g_fused[(size_t)BATCH * EMB * HW];
__device__ float  g_gout [(size_t)BATCH * EMB * HW];
__device__ float  g_avg  [BATCH * EMB];
__device__ float  g_max  [BATCH * EMB];
__device__ float  g_attn [BATCH * EMB];
__device__ __half g_xh   [(size_t)BATCH * CB16 * HW * 16];  // [b][cb][h][w][c16]
__device__ __half g_fh   [(size_t)BATCH * ECB * HW * 16];   // fused*attn fp16
__device__ __half g_wh3  [9  * EB * CIN];                   // [tap][oc][c]
__device__ __half g_wh5  [25 * EB * CIN];
__device__ __half g_wh7  [49 * EB * CIN];
__device__ __half g_wfh  [EMB * EMB];                       // fusion weights fp16 [o][c]

// ---- helpers ---------------------------------------------------------------
__device__ __forceinline__ void mma_f16(float& d0, float& d1, float& d2, float& d3,
                                        unsigned a0, unsigned a1, unsigned a2, unsigned a3,
                                        unsigned b0, unsigned b1) {
    asm("mma.sync.aligned.m16n8k16.row.col.f32.f16.f16.f32 "
        "{%0,%1,%2,%3}, {%4,%5,%6,%7}, {%8,%9}, {%0,%1,%2,%3};"
        : "+f"(d0), "+f"(d1), "+f"(d2), "+f"(d3)
        : "r"(a0), "r"(a1), "r"(a2), "r"(a3), "r"(b0), "r"(b1));
}
__device__ __forceinline__ void ldsm_x4(unsigned& r0, unsigned& r1, unsigned& r2, unsigned& r3,
                                        unsigned addr) {
    asm volatile("ldmatrix.sync.aligned.m8n8.x4.shared.b16 {%0,%1,%2,%3}, [%4];"
                 : "=r"(r0), "=r"(r1), "=r"(r2), "=r"(r3) : "r"(addr));
}
__device__ __forceinline__ void cpa16(unsigned dst, const void* src, unsigned srcbytes) {
    asm volatile("cp.async.cg.shared.global [%0], [%1], 16, %2;"
                 :: "r"(dst), "l"(src), "r"(srcbytes) : "memory");
}
__device__ __forceinline__ void cpa_commit() {
    asm volatile("cp.async.commit_group;" ::: "memory");
}
template<int N>
__device__ __forceinline__ void cpa_wait() {
    asm volatile("cp.async.wait_group %0;" :: "n"(N) : "memory");
}

// ---------------------------------------------------------------------------
// Pre-pass: x [B][C][H][W] fp32 -> g_xh [b][cb][h][w][c16] fp16
// ---------------------------------------------------------------------------
__global__ __launch_bounds__(256)
void prep_xh_kernel(const float* __restrict__ x, __half* __restrict__ xh)
{
    __shared__ __half s[16][129];
    const int hw0 = blockIdx.x * 128;
    const int cb  = blockIdx.y;
    const int b   = blockIdx.z;
    const int t   = threadIdx.x;

#pragma unroll
    for (int p = 0; p < 8; ++p) {
        int ci = p * 2 + (t >> 7);
        int j  = t & 127;
        s[ci][j] = __float2half(x[((size_t)(b * CIN + cb * 16 + ci)) * HW + hw0 + j]);
    }
    __syncthreads();

    int j    = t >> 1;
    int csel = t & 1;
    __half tmp[8];
#pragma unroll
    for (int k = 0; k < 8; ++k) tmp[k] = s[csel * 8 + k][j];
    *reinterpret_cast<uint4*>(&xh[(((size_t)(b * CB16 + cb)) * HW + hw0 + j) * 16 + csel * 8]) =
        *reinterpret_cast<uint4*>(tmp);
}

// Pre-pass: fused*attn fp32 -> g_fh [b][cb][hw][c16] fp16
__global__ __launch_bounds__(256)
void prep_fh_kernel(const float* __restrict__ fused, const float* __restrict__ attn,
                    __half* __restrict__ fh)
{
    __shared__ __half s[16][129];
    const int hw0 = blockIdx.x * 128;
    const int cb  = blockIdx.y;
    const int b   = blockIdx.z;
    const int t   = threadIdx.x;

#pragma unroll
    for (int p = 0; p < 8; ++p) {
        int ci = p * 2 + (t >> 7);
        int j  = t & 127;
        int c  = cb * 16 + ci;
        s[ci][j] = __float2half(fused[((size_t)(b * EMB + c)) * HW + hw0 + j] *
                                attn[b * EMB + c]);
    }
    __syncthreads();

    int j    = t >> 1;
    int csel = t & 1;
    __half tmp[8];
#pragma unroll
    for (int k = 0; k < 8; ++k) tmp[k] = s[csel * 8 + k][j];
    *reinterpret_cast<uint4*>(&fh[(((size_t)(b * ECB + cb)) * HW + hw0 + j) * 16 + csel * 8]) =
        *reinterpret_cast<uint4*>(tmp);
}

// Pre-pass: w [oc][c][kk] fp32 -> wh [kk][oc][c] fp16
__global__ __launch_bounds__(256)
void prep_wh_kernel(const float* __restrict__ w, __half* __restrict__ wh, int kkN)
{
    int idx = blockIdx.x * 256 + threadIdx.x;
    int total = kkN * EB * CIN;
    if (idx < total) {
        int c  = idx & 127;
        int oc = (idx >> 7) & 127;
        int kk = idx >> 14;
        wh[idx] = __float2half(w[((size_t)oc * CIN + c) * kkN + kk]);
    }
}

// Pre-pass: fusion weights fp32 -> fp16
__global__ __launch_bounds__(256)
void prep_wfh_kernel(const float* __restrict__ w, __half* __restrict__ wh)
{
    int idx = blockIdx.x * 256 + threadIdx.x;
    if (idx < EMB * EMB) wh[idx] = __float2half(w[idx]);
}

// ---------------------------------------------------------------------------
// Conv via fp16 mma m16n8k16 + ldmatrix + cp.async pipeline.
//  - stages s = (c-block, kh-group); 3-stage cp.async weight pipeline,
//    2-buffer zfill input staging; ONE __syncthreads per stage
//  - per tap per warp: 2 A-ldsm.x4 + 4 B-ldsm.x4 + 16 mma (32oc x 64sp)
// ---------------------------------------------------------------------------
template<int K, int ROWS, int OCB>
__global__ __launch_bounds__(256, 2)
void conv_f16_kernel(const __half* __restrict__ xh, const __half* __restrict__ wh,
                     const float* __restrict__ bias, float* __restrict__ out, int ch_off)
{
    constexpr int HALO    = K / 2;
    constexpr int WIN     = WW + K - 1;
    constexpr int IN_ROWS = ROWS + K - 1;
    constexpr int NOG     = OCB / 32;
    constexpr int NSG     = 8 / NOG;       // == ROWS
    constexpr int NITEM   = K * OCB;       // 32B weight granules per stage
    constexpr int WCH     = NITEM * 2;     // 16B chunks per weight stage
    constexpr int NWPF    = (WCH + 255) / 256;
    constexpr int NCHUNK  = IN_ROWS * WIN * 2;
    constexpr int SINB    = IN_ROWS * WIN * 32;   // bytes per input buffer
    constexpr int SWB     = K * OCB * 32;         // bytes per weight buffer
    constexpr int S       = CB16 * K;             // total stages

    extern __shared__ __align__(128) unsigned char dsm[];
    const unsigned base = (unsigned)__cvta_generic_to_shared(dsm);
    const unsigned sin_base[2] = { base, base + SINB };
    const unsigned sw_base [3] = { base + 2 * SINB,
                                   base + 2 * SINB + SWB,
                                   base + 2 * SINB + 2 * SWB };

    const int h0     = blockIdx.x * ROWS;
    const int b      = blockIdx.y;
    const int ocbase = blockIdx.z * OCB;
    const int t      = threadIdx.x;
    const int warp   = t >> 5;
    const int lane   = t & 31;
    const int gid    = lane >> 2;
    const int tig    = lane & 3;
    const int ocg    = warp / NSG;
    const int rw     = warp % NSG;

    float d[2][8][4];
#pragma unroll
    for (int mm = 0; mm < 2; ++mm)
#pragma unroll
        for (int n = 0; n < 8; ++n)
#pragma unroll
            for (int j = 0; j < 4; ++j) d[mm][n][j] = 0.f;

    // fragment lane-address components
    const int laneA  = lane & 15;
    const int cselA  = (lane >> 4) & 1;
    const int laneB4 = (lane & 7) | (((lane >> 4) & 1) << 3);
    const int cselB4 = (lane >> 3) & 1;

    const __half* xbase = xh + ((size_t)(b * CB16)) * HW * 16;

    // ---- staging helpers -----------------------------------------------
    auto issue_w = [&](int s2) {
        if (s2 >= S) return;
        const int cb2 = s2 / K;
        const int g2  = s2 - cb2 * K;
        const unsigned dstb = sw_base[s2 % 3];
#pragma unroll
        for (int j = 0; j < NWPF; ++j) {
            int q = t + j * 256;
            if (q < WCH) {
                int it = q >> 1, half = q & 1;
                int tap = it / OCB, oc = it - tap * OCB;
                const __half* src = wh + ((size_t)(g2 * K + tap) * EB + ocbase + oc) * CIN
                                       + cb2 * 16 + half * 8;
                unsigned off = (unsigned)(it * 32 + half * 16) ^ ((it & 4) << 2);
                cpa16(dstb + off, src, 16);
            }
        }
    };
    auto issue_in = [&](int cb) {
        const __half* xc = xbase + (size_t)cb * HW * 16;
        const unsigned dstb = sin_base[cb & 1];
        for (int q = t; q < NCHUNK; q += 256) {
            int n = q >> 1, cs = q & 1;
            int r = n / WIN, col = n - r * WIN;
            int gr = h0 + r - HALO, gw = col - HALO;
            bool inb = ((unsigned)gr < HH) && ((unsigned)gw < WW);
            const __half* src = inb ? (xc + ((size_t)gr * WW + gw) * 16 + cs * 8) : xc;
            unsigned off = (unsigned)(n * 32 + cs * 16) ^ ((n & 4) << 2);
            cpa16(dstb + off, src, inb ? 16u : 0u);
        }
    };

    // ---- prologue: groups for stages 0 and 1 ----------------------------
    issue_w(0); issue_in(0); cpa_commit();
    issue_w(1); cpa_commit();

    for (int s = 0; s < S; ++s) {
        const int cb = s / K;
        const int g  = s - cb * K;

        cpa_wait<1>();       // group s complete (W(s); and IN(cb) issued <= s-2)
        __syncthreads();     // all threads ready; closes stage s-1 reads

        issue_w(s + 2);
        if (g == K - 2 && cb + 1 < CB16) issue_in(cb + 1);
        cpa_commit();

        const unsigned swb  = sw_base[s % 3];
        const unsigned sinb = sin_base[cb & 1];
        const int rowbase = (rw + g) * WIN;
#pragma unroll
        for (int kw = 0; kw < K; ++kw) {
            unsigned a[2][4];
#pragma unroll
            for (int mm = 0; mm < 2; ++mm) {
                int gA = kw * OCB + ocg * 32 + mm * 16 + laneA;
                unsigned offA = (unsigned)(gA * 32 + cselA * 16) ^ ((gA & 4) << 2);
                ldsm_x4(a[mm][0], a[mm][1], a[mm][2], a[mm][3], swb + offA);
            }
#pragma unroll
            for (int ntp = 0; ntp < 4; ++ntp) {
                int gB = rowbase + ntp * 16 + laneB4 + kw;
                unsigned offB = (unsigned)(gB * 32 + cselB4 * 16) ^ ((gB & 4) << 2);
                unsigned b0, b1, b2, b3;
                ldsm_x4(b0, b1, b2, b3, sinb + offB);
                const int n0 = ntp * 2;
                mma_f16(d[0][n0][0], d[0][n0][1], d[0][n0][2], d[0][n0][3],
                        a[0][0], a[0][1], a[0][2], a[0][3], b0, b1);
                mma_f16(d[1][n0][0], d[1][n0][1], d[1][n0][2], d[1][n0][3],
                        a[1][0], a[1][1], a[1][2], a[1][3], b0, b1);
                mma_f16(d[0][n0+1][0], d[0][n0+1][1], d[0][n0+1][2], d[0][n0+1][3],
                        a[0][0], a[0][1], a[0][2], a[0][3], b2, b3);
                mma_f16(d[1][n0+1][0], d[1][n0+1][1], d[1][n0+1][2], d[1][n0+1][3],
                        a[1][0], a[1][1], a[1][2], a[1][3], b2, b3);
            }
        }
    }

    // ---- epilogue ----
    const int h = h0 + rw;
#pragma unroll
    for (int mm = 0; mm < 2; ++mm) {
        int oc0 = ocbase + ocg * 32 + mm * 16 + gid;
        float bv0 = bias[oc0];
        float bv1 = bias[oc0 + 8];
#pragma unroll
        for (int n = 0; n < 8; ++n) {
            int w0 = n * 8 + tig * 2;
            float* p0 = out + (((size_t)b * EMB + ch_off + oc0) * HH + h) * WW + w0;
            float* p1 = p0 + (size_t)8 * HW;
            *reinterpret_cast<float2*>(p0) = make_float2(d[mm][n][0] + bv0, d[mm][n][1] + bv0);
            *reinterpret_cast<float2*>(p1) = make_float2(d[mm][n][2] + bv1, d[mm][n][3] + bv1);
        }
    }
}

// ---------------------------------------------------------------------------
// Fusion 1x1 conv as fp16 GEMM.
// ---------------------------------------------------------------------------
__global__ __launch_bounds__(256)
void gemm_f16_kernel(const __half* __restrict__ fh, const __half* __restrict__ wfh,
                     const float* __restrict__ fb, float* __restrict__ out)
{
    __shared__ __align__(128) unsigned char sA[2][4096];
    __shared__ __align__(128) unsigned char sB[2][4096];

    const int obase = blockIdx.x * 128;
    const int hw0   = blockIdx.y * 128;
    const int b     = blockIdx.z;
    const int t     = threadIdx.x;
    const int warp  = t >> 5;
    const int lane  = t & 31;
    const int gid   = lane >> 2;
    const int tig   = lane & 3;
    const int ocg   = warp >> 1;
    const int hwg   = warp & 1;

    const unsigned sAb[2] = { (unsigned)__cvta_generic_to_shared(sA[0]),
                              (unsigned)__cvta_generic_to_shared(sA[1]) };
    const unsigned sBb[2] = { (unsigned)__cvta_generic_to_shared(sB[0]),
                              (unsigned)__cvta_generic_to_shared(sB[1]) };

    const int laneA  = lane & 15;
    const int cselA  = (lane >> 4) & 1;
    const int laneB4 = (lane & 7) | (((lane >> 4) & 1) << 3);
    const int cselB4 = (lane >> 3) & 1;

    float d[2][8][4];
#pragma unroll
    for (int mm = 0; mm < 2; ++mm)
#pragma unroll
        for (int n = 0; n < 8; ++n)
#pragma unroll
            for (int j = 0; j < 4; ++j) d[mm][n][j] = 0.f;

    const int grow = t >> 1;
    const int gcs  = t & 1;
    const unsigned stoff = (unsigned)(grow * 32 + gcs * 16) ^ ((grow & 4) << 2);

    const __half* Asrc = wfh + (size_t)(obase + grow) * EMB + gcs * 8;
    const __half* Bsrc = fh + ((size_t)b * ECB * HW + hw0 + grow) * 16 + gcs * 8;

    uint4 av = *reinterpret_cast<const uint4*>(Asrc);
    uint4 bv = *reinterpret_cast<const uint4*>(Bsrc);

    for (int cb = 0; cb < ECB; ++cb) {
        const int p = cb & 1;
        *reinterpret_cast<uint4*>(sA[p] + stoff) = av;
        *reinterpret_cast<uint4*>(sB[p] + stoff) = bv;
        if (cb + 1 < ECB) {
            av = *reinterpret_cast<const uint4*>(Asrc + (cb + 1) * 16);
            bv = *reinterpret_cast<const uint4*>(Bsrc + (size_t)(cb + 1) * HW * 16);
        }
        __syncthreads();

        unsigned a[2][4];
#pragma unroll
        for (int mm = 0; mm < 2; ++mm) {
            int gA = ocg * 32 + mm * 16 + laneA;
            unsigned offA = (unsigned)(gA * 32 + cselA * 16) ^ ((gA & 4) << 2);
            ldsm_x4(a[mm][0], a[mm][1], a[mm][2], a[mm][3], sAb[p] + offA);
        }
        const int rowbase = hwg * 64;
#pragma unroll
        for (int ntp = 0; ntp < 4; ++ntp) {
            int gB = rowbase + ntp * 16 + laneB4;
            unsigned offB = (unsigned)(gB * 32 + cselB4 * 16) ^ ((gB & 4) << 2);
            unsigned b0, b1, b2, b3;
            ldsm_x4(b0, b1, b2, b3, sBb[p] + offB);
            const int n0 = ntp * 2;
            mma_f16(d[0][n0][0], d[0][n0][1], d[0][n0][2], d[0][n0][3],
                    a[0][0], a[0][1], a[0][2], a[0][3], b0, b1);
            mma_f16(d[1][n0][0], d[1][n0][1], d[1][n0][2], d[1][n0][3],
                    a[1][0], a[1][1], a[1][2], a[1][3], b0, b1);
            mma_f16(d[0][n0+1][0], d[0][n0+1][1], d[0][n0+1][2], d[0][n0+1][3],
                    a[0][0], a[0][1], a[0][2], a[0][3], b2, b3);
            mma_f16(d[1][n0+1][0], d[1][n0+1][1], d[1][n0+1][2], d[1][n0+1][3],
                    a[1][0], a[1][1], a[1][2], a[1][3], b2, b3);
        }
    }

#pragma unroll
    for (int mm = 0; mm < 2; ++mm) {
        int oc0 = obase + ocg * 32 + mm * 16 + gid;
        float bv0 = fb[oc0];
        float bv1 = fb[oc0 + 8];
#pragma unroll
        for (int n = 0; n < 8; ++n) {
            int col = hw0 + hwg * 64 + n * 8 + tig * 2;
            float* p0 = out + ((size_t)b * EMB + oc0) * HW + col;
            float* p1 = p0 + (size_t)8 * HW;
            *reinterpret_cast<float2*>(p0) = make_float2(d[mm][n][0] + bv0, d[mm][n][1] + bv0);
            *reinterpret_cast<float2*>(p1) = make_float2(d[mm][n][2] + bv1, d[mm][n][3] + bv1);
        }
    }
}

// ---------------------------------------------------------------------------
// Global avg + max pool per (b, e).
// ---------------------------------------------------------------------------
__global__ __launch_bounds__(256)
void pool_kernel(const float* __restrict__ fused,
                 float* __restrict__ avg_out, float* __restrict__ max_out)
{
    const int e = blockIdx.x;
    const int b = blockIdx.y;
    const int t = threadIdx.x;

    const float4* p = reinterpret_cast<const float4*>(fused + ((size_t)b * EMB + e) * HW);

    float s = 0.f, m = -INFINITY;
#pragma unroll
    for (int i = 0; i < 4; ++i) {
        float4 v = p[t + i * 256];
        s += v.x + v.y + v.z + v.w;
        m = fmaxf(m, fmaxf(fmaxf(v.x, v.y), fmaxf(v.z, v.w)));
    }

    __shared__ float ss[256], sm[256];
    ss[t] = s; sm[t] = m;
    __syncthreads();
    for (int o = 128; o > 0; o >>= 1) {
        if (t < o) { ss[t] += ss[t + o]; sm[t] = fmaxf(sm[t], sm[t + o]); }
        __syncthreads();
    }
    if (t == 0) {
        avg_out[b * EMB + e] = ss[0] * (1.f / (float)HW);
        max_out[b * EMB + e] = sm[0];
    }
}

// ---------------------------------------------------------------------------
// CBAM MLP + sigmoid.
// ---------------------------------------------------------------------------
__global__ __launch_bounds__(EMB)
void attn_kernel(const float* __restrict__ avg_in, const float* __restrict__ max_in,
                 const float* __restrict__ w1, const float* __restrict__ w2,
                 float* __restrict__ attn)
{
    const int b = blockIdx.x;
    const int t = threadIdx.x;

    __shared__ float s_avg[EMB], s_max[EMB];
    __shared__ float s_h[HID];
    __shared__ float s_ha[HID], s_hm[HID];

    s_avg[t] = avg_in[b * EMB + t];
    s_max[t] = max_in[b * EMB + t];
    __syncthreads();

    if (t < HID) {
        float a = 0.f;
        const float* w1r = w1 + t * EMB;
        for (int e = 0; e < EMB; ++e) a = fmaf(s_avg[e], w1r[e], a);
        s_ha[t] = fmaxf(a, 0.f);
    } else if (t >= 32 && t < 32 + HID) {
        int j = t - 32;
        float a = 0.f;
        const float* w1r = w1 + j * EMB;
        for (int e = 0; e < EMB; ++e) a = fmaf(s_max[e], w1r[e], a);
        s_hm[j] = fmaxf(a, 0.f);
    }
    __syncthreads();
    if (t < HID) s_h[t] = s_ha[t] + s_hm[t];
    __syncthreads();

    float v = 0.f;
    const float* w2r = w2 + t * HID;
#pragma unroll
    for (int j = 0; j < HID; ++j) v = fmaf(s_h[j], w2r[j], v);
    attn[b * EMB + t] = 1.f / (1.f + expf(-v));
}

// ---------------------------------------------------------------------------
// Transpose [B,E,HW] -> [B,HW,E] + LayerNorm over E.
// ---------------------------------------------------------------------------
__global__ __launch_bounds__(256)
void ln_kernel(const float* __restrict__ g, const float* __restrict__ gamma,
               const float* __restrict__ beta, float* __restrict__ out)
{
    __shared__ float s[EMB * 17];

    const int hw0 = blockIdx.x * 16;
    const int b   = blockIdx.y;
    const int t   = threadIdx.x;

    const float* gb = g + (size_t)b * EMB * HW + hw0;
    for (int i = t; i < EMB * 16; i += 256) {
        int e   = i >> 4;
        int tok = i & 15;
        s[e * 17 + tok] = gb[(size_t)e * HW + tok];
    }
    __syncthreads();

    const int warp = t >> 5;
    const int lane = t & 31;

#pragma unroll
    for (int tt = 0; tt < 2; ++tt) {
        int tok = warp * 2 + tt;
        float vals[12];
        float sum = 0.f, sq = 0.f;
#pragma unroll
        for (int k = 0; k < 12; ++k) {
            float v = s[(lane + 32 * k) * 17 + tok];
            vals[k] = v;
            sum += v;
            sq  = fmaf(v, v, sq);
        }
#pragma unroll
        for (int o = 16; o > 0; o >>= 1) {
            sum += __shfl_xor_sync(0xFFFFFFFFu, sum, o);
            sq  += __shfl_xor_sync(0xFFFFFFFFu, sq,  o);
        }
        float mu  = sum * (1.f / (float)EMB);
        float var = sq * (1.f / (float)EMB) - mu * mu;
        float rstd = rsqrtf(var + 1e-5f);

        float* dst = out + ((size_t)b * HW + hw0 + tok) * EMB;
#pragma unroll
        for (int k = 0; k < 12; ++k) {
            int e = lane + 32 * k;
            dst[e] = (vals[k] - mu) * rstd * gamma[e] + beta[e];
        }
    }
}

// ---------------------------------------------------------------------------
// Launcher.
// ---------------------------------------------------------------------------
extern "C" void kernel_launch(void* const* d_in, const int* in_sizes, int n_in,
                              void* d_out, int out_size)
{
    const float* x   = (const float*)d_in[0];
    const float* w3  = (const float*)d_in[1];
    const float* b3  = (const float*)d_in[2];
    const float* w5  = (const float*)d_in[3];
    const float* b5  = (const float*)d_in[4];
    const float* w7  = (const float*)d_in[5];
    const float* b7  = (const float*)d_in[6];
    const float* cw1 = (const float*)d_in[7];
    const float* cw2 = (const float*)d_in[8];
    const float* fw  = (const float*)d_in[9];
    const float* fbi = (const float*)d_in[10];
    const float* lng = (const float*)d_in[11];
    const float* lnb = (const float*)d_in[12];
    float* out = (float*)d_out;

    float* fused; cudaGetSymbolAddress((void**)&fused, g_fused);
    float* gout;  cudaGetSymbolAddress((void**)&gout,  g_gout);
    float* gavg;  cudaGetSymbolAddress((void**)&gavg,  g_avg);
    float* gmax;  cudaGetSymbolAddress((void**)&gmax,  g_max);
    float* gattn; cudaGetSymbolAddress((void**)&gattn, g_attn);
    __half* xh;  cudaGetSymbolAddress((void**)&xh,  g_xh);
    __half* fh;  cudaGetSymbolAddress((void**)&fh,  g_fh);
    __half* wh3; cudaGetSymbolAddress((void**)&wh3, g_wh3);
    __half* wh5; cudaGetSymbolAddress((void**)&wh5, g_wh5);
    __half* wh7; cudaGetSymbolAddress((void**)&wh7, g_wh7);
    __half* wfh; cudaGetSymbolAddress((void**)&wfh, g_wfh);

    // dynamic smem: 2*(input buf) + 3*(weight buf)
    constexpr int SM3 = 2 * (4  * 66 * 32) + 3 * (3 * 128 * 32);   // 53760
    constexpr int SM5 = 2 * (6  * 68 * 32) + 3 * (5 * 128 * 32);   // 87552
    constexpr int SM7 = 2 * (10 * 70 * 32) + 3 * (7 * 64  * 32);   // 87808
    cudaFuncSetAttribute(conv_f16_kernel<3, 2, 128>, cudaFuncAttributeMaxDynamicSharedMemorySize, SM3);
    cudaFuncSetAttribute(conv_f16_kernel<5, 2, 128>, cudaFuncAttributeMaxDynamicSharedMemorySize, SM5);
    cudaFuncSetAttribute(conv_f16_kernel<7, 4, 64>,  cudaFuncAttributeMaxDynamicSharedMemorySize, SM7);

    // pre-pass conversions
    prep_xh_kernel<<<dim3(HW / 128, CB16, BATCH), 256>>>(x, xh);
    prep_wh_kernel<<<(9  * EB * CIN + 255) / 256, 256>>>(w3, wh3, 9);
    prep_wh_kernel<<<(25 * EB * CIN + 255) / 256, 256>>>(w5, wh5, 25);
    prep_wh_kernel<<<(49 * EB * CIN + 255) / 256, 256>>>(w7, wh7, 49);
    prep_wfh_kernel<<<(EMB * EMB + 255) / 256, 256>>>(fw, wfh);

    // convs
    conv_f16_kernel<3, 2, 128><<<dim3(HH / 2, BATCH, 1), 256, SM3>>>(xh, wh3, b3, fused, 0);
    conv_f16_kernel<5, 2, 128><<<dim3(HH / 2, BATCH, 1), 256, SM5>>>(xh, wh5, b5, fused, EB);
    conv_f16_kernel<7, 4, 64><<<dim3(HH / 4, BATCH, 2), 256, SM7>>>(xh, wh7, b7, fused, 2 * EB);

    pool_kernel<<<dim3(EMB, BATCH), 256>>>(fused, gavg, gmax);
    attn_kernel<<<BATCH, EMB>>>(gavg, gmax, cw1, cw2, gattn);

    prep_fh_kernel<<<dim3(HW / 128, ECB, BATCH), 256>>>(fused, gattn, fh);
    gemm_f16_kernel<<<dim3(EMB / 128, HW / 128, BATCH), 256>>>(fh, wfh, fbi, gout);

    ln_kernel<<<dim3(HW / 16, BATCH), 256>>>(gout, lng, lnb, out);
}